// round 13
// baseline (speedup 1.0000x reference)
#include <cuda_runtime.h>
#include <cuda_bf16.h>
#include <cstdint>
#include <cstddef>

typedef unsigned long long ull;

__device__ __forceinline__ void ffma2(ull& d, ull a, ull b){
    asm("fma.rn.f32x2 %0, %1, %2, %0;" : "+l"(d) : "l"(a), "l"(b));
}
__device__ __forceinline__ ull pk2(float x, float y){
    ull r; asm("mov.b64 %0, {%1, %2};" : "=l"(r) : "f"(x), "f"(y)); return r;
}
__device__ __forceinline__ float2 upk(ull a){
    float2 r; asm("mov.b64 {%0, %1}, %2;" : "=f"(r.x), "=f"(r.y) : "l"(a)); return r;
}

#define LDSM4(r, addr) asm volatile( \
    "ldmatrix.sync.aligned.m8n8.x4.shared.b16 {%0,%1,%2,%3}, [%4];" \
    : "=r"((r)[0]),"=r"((r)[1]),"=r"((r)[2]),"=r"((r)[3]) : "r"(addr))

#define MMA16816(c, a, b) asm volatile( \
    "mma.sync.aligned.m16n8k16.row.col.f32.bf16.bf16.f32 " \
    "{%0,%1,%2,%3}, {%4,%5,%6,%7}, {%8,%9}, {%0,%1,%2,%3};" \
    : "+f"((c)[0]),"+f"((c)[1]),"+f"((c)[2]),"+f"((c)[3]) \
    : "r"((a)[0]),"r"((a)[1]),"r"((a)[2]),"r"((a)[3]), "r"((b)[0]),"r"((b)[1]))

#define CP16(dst, src) asm volatile( \
    "cp.async.cg.shared.global [%0], [%1], 16;" :: "r"(dst), "l"(src))

// ---------------- fixed shapes ----------------
#define BB 4
#define HF 128
#define WF 128
#define CF 256
#define HC 64
#define WC 64
#define CC 512
#define EE 64
#define FF 256
#define NP 384
#define NCOARSE (BB*HC*WC)   // 16384
#define NFINE   (BB*HF*WF)   // 65536

// ---------------- scratch ----------------
__device__ __nv_bfloat16 g_cnh[(size_t)NCOARSE*CC];
__device__ __nv_bfloat16 g_cnl[(size_t)NCOARSE*CC];
__device__ __nv_bfloat16 g_wth[(size_t)NP*CC];
__device__ __nv_bfloat16 g_wtl[(size_t)NP*CC];
__device__ __nv_bfloat16 g_fh[(size_t)NFINE*CF];
__device__ __nv_bfloat16 g_fl[(size_t)NFINE*CF];
__device__ __nv_bfloat16 g_wqh[(size_t)EE*CF];
__device__ __nv_bfloat16 g_wql[(size_t)EE*CF];
__device__ float g_gate[NCOARSE];
__device__ float g_proj[(size_t)NCOARSE*NP];
__device__ float g_query[(size_t)NFINE*EE];
__device__ float g_mean[NFINE];
__device__ float g_rstd[NFINE];
__device__ float g_dvec[EE];
__device__ float g_cvec[EE];
__device__ float g_bcat[NP];

__device__ __forceinline__ void split4(float4 v, uint2& hi, uint2& lo){
    __nv_bfloat16 hx=__float2bfloat16_rn(v.x), hy=__float2bfloat16_rn(v.y);
    __nv_bfloat16 hz=__float2bfloat16_rn(v.z), hw=__float2bfloat16_rn(v.w);
    __nv_bfloat16 lx=__float2bfloat16_rn(v.x-__bfloat162float(hx));
    __nv_bfloat16 ly=__float2bfloat16_rn(v.y-__bfloat162float(hy));
    __nv_bfloat16 lz=__float2bfloat16_rn(v.z-__bfloat162float(hz));
    __nv_bfloat16 lw=__float2bfloat16_rn(v.w-__bfloat162float(hw));
    __nv_bfloat162 h01; h01.x=hx; h01.y=hy;
    __nv_bfloat162 h23; h23.x=hz; h23.y=hw;
    __nv_bfloat162 l01; l01.x=lx; l01.y=ly;
    __nv_bfloat162 l23; l23.x=lz; l23.y=lw;
    hi.x=*(unsigned*)&h01; hi.y=*(unsigned*)&h23;
    lo.x=*(unsigned*)&l01; lo.y=*(unsigned*)&l23;
}

// ================= kernel 1: LN(coarse) + gate, emit bf16 hi/lo =================
__global__ void __launch_bounds__(128) ln_coarse_gate(
    const float* __restrict__ x, const float* __restrict__ g, const float* __restrict__ b,
    const float* __restrict__ wg, const float* __restrict__ bg)
{
    int row = blockIdx.x; int t = threadIdx.x;
    const float4* xr = (const float4*)(x + (size_t)row*CC);
    float4 v = xr[t];
    float s  = v.x+v.y+v.z+v.w;
    float sq = v.x*v.x+v.y*v.y+v.z*v.z+v.w*v.w;
    #pragma unroll
    for (int o=16;o;o>>=1){ s += __shfl_xor_sync(0xffffffffu,s,o); sq += __shfl_xor_sync(0xffffffffu,sq,o); }
    __shared__ float red[8];
    int wid = t>>5, l = t&31;
    if (l==0){ red[wid]=s; red[4+wid]=sq; }
    __syncthreads();
    s  = red[0]+red[1]+red[2]+red[3];
    sq = red[4]+red[5]+red[6]+red[7];
    float mean = s*(1.f/512.f);
    float var  = sq*(1.f/512.f) - mean*mean;
    float rstd = rsqrtf(var + 1e-3f);
    float4 gv = ((const float4*)g)[t];
    float4 bv = ((const float4*)b)[t];
    float4 o;
    o.x = (v.x-mean)*rstd*gv.x + bv.x;
    o.y = (v.y-mean)*rstd*gv.y + bv.y;
    o.z = (v.z-mean)*rstd*gv.z + bv.z;
    o.w = (v.w-mean)*rstd*gv.w + bv.w;
    uint2 uh, ulo;
    split4(o, uh, ulo);
    size_t off = (size_t)row*CC + t*4;
    *(uint2*)&g_cnh[off] = uh;
    *(uint2*)&g_cnl[off] = ulo;

    float4 wv = ((const float4*)wg)[t];
    float gd = o.x*wv.x + o.y*wv.y + o.z*wv.z + o.w*wv.w;
    #pragma unroll
    for (int oo=16;oo;oo>>=1) gd += __shfl_xor_sync(0xffffffffu,gd,oo);
    __syncthreads();
    if (l==0) red[wid]=gd;
    __syncthreads();
    if (t==0){
        float tot = red[0]+red[1]+red[2]+red[3] + bg[0];
        g_gate[row] = 1.f/(1.f+__expf(-tot));
    }
}

// ================= kernel 2: fine LN stats + bf16 hi/lo emit =================
__global__ void __launch_bounds__(256) fine_stats(const float* __restrict__ x)
{
    int w = threadIdx.x>>5, l = threadIdx.x&31;
    int row = blockIdx.x*8 + w;
    const float4* xr = (const float4*)(x + (size_t)row*CF);
    float4 a = xr[l], c = xr[l+32];
    float s  = a.x+a.y+a.z+a.w + c.x+c.y+c.z+c.w;
    float sq = a.x*a.x+a.y*a.y+a.z*a.z+a.w*a.w + c.x*c.x+c.y*c.y+c.z*c.z+c.w*c.w;
    #pragma unroll
    for (int o=16;o;o>>=1){ s += __shfl_xor_sync(0xffffffffu,s,o); sq += __shfl_xor_sync(0xffffffffu,sq,o); }
    if (l==0){
        float m = s*(1.f/256.f);
        g_mean[row] = m;
        g_rstd[row] = rsqrtf(sq*(1.f/256.f) - m*m + 1e-3f);
    }
    uint2 ah, al, ch, cl;
    split4(a, ah, al);
    split4(c, ch, cl);
    size_t off = (size_t)row*CF + l*4;
    *(uint2*)&g_fh[off]       = ah;
    *(uint2*)&g_fl[off]       = al;
    *(uint2*)&g_fh[off + 128] = ch;
    *(uint2*)&g_fl[off + 128] = cl;
}

// ================= pack weights: W^T hi/lo bf16 + bias =================
__global__ void __launch_bounds__(384) pack_w(
    const float* __restrict__ wk, const float* __restrict__ wqc, const float* __restrict__ wv,
    const float* __restrict__ bk, const float* __restrict__ bqc, const float* __restrict__ bv)
{
    int k = blockIdx.x; int n = threadIdx.x;
    float v;
    if (n < 64)       v = wk [k*64  + n];
    else if (n < 128) v = wqc[k*64  + (n-64)];
    else              v = wv [k*256 + (n-128)];
    __nv_bfloat16 hi = __float2bfloat16_rn(v);
    __nv_bfloat16 lo = __float2bfloat16_rn(v - __bfloat162float(hi));
    g_wth[(size_t)n*CC + k] = hi;
    g_wtl[(size_t)n*CC + k] = lo;
    if (k == 0){
        float bvv = (n<64) ? bk[n] : (n<128) ? bqc[n-64] : bv[n-128];
        g_bcat[n] = bvv;
    }
}

// ================= fold LN(fine) params into w_qf (bf16 hi/lo [n][k]) =================
__global__ void __launch_bounds__(256) fold_qf(
    const float* __restrict__ wqf, const float* __restrict__ bqf,
    const float* __restrict__ g, const float* __restrict__ bb)
{
    int n = blockIdx.x; int t = threadIdx.x;
    float wv = wqf[t*EE + n];
    float wf = g[t]*wv;
    __nv_bfloat16 hi = __float2bfloat16_rn(wf);
    __nv_bfloat16 lo = __float2bfloat16_rn(wf - __bfloat162float(hi));
    g_wqh[(size_t)n*CF + t] = hi;
    g_wql[(size_t)n*CF + t] = lo;
    float cv = bb[t]*wv;
    float wfs = wf;
    #pragma unroll
    for (int o=16;o;o>>=1){ wfs += __shfl_xor_sync(0xffffffffu,wfs,o); cv += __shfl_xor_sync(0xffffffffu,cv,o); }
    __shared__ float sd[8], sc[8];
    int wid = t>>5, l = t&31;
    if (l==0){ sd[wid]=wfs; sc[wid]=cv; }
    __syncthreads();
    if (t==0){
        float dd=0.f, cc=0.f;
        #pragma unroll
        for (int i=0;i<8;i++){ dd+=sd[i]; cc+=sc[i]; }
        g_dvec[n]=dd; g_cvec[n]=cc + bqf[n];
    }
}

// ================= projection GEMM: BM=128 BN=64 BK=32, grid 768 (wave-balance) =================
// Per buffer: Ah 10240 | Al 10240 | Bh 5120 | Bl 5120 = 30720B; x2 = 61440B dynamic.
#define QROW 40
#define QAH 0
#define QAL 10240
#define QBH 20480
#define QBL 25600
#define QBUF 30720
#define GEMM_SMEM 61440
__global__ void __launch_bounds__(256,2) proj_gemm()
{
    extern __shared__ __align__(16) char smraw[];
    uint32_t sb = (uint32_t)__cvta_generic_to_shared(smraw);
    int t = threadIdx.x;
    int n0 = blockIdx.x*64, m0 = blockIdx.y*128;
    int w = t>>5, l = t&31;
    int wm = w>>1, wn = w&1;
    int m0w = wm*32, n0w = wn*32;

    // A staging: 128 rows, 2 thr/row, 16 elems each
    int sr = t>>1, skh = (t&1)*16;
    const __nv_bfloat16* gAh = g_cnh + (size_t)(m0+sr)*CC + skh;
    const __nv_bfloat16* gAl = g_cnl + (size_t)(m0+sr)*CC + skh;
    uint32_t doffA = (uint32_t)(sr*QROW + skh)*2;
    // B staging: 64 rows, 4 thr/row, 8 elems each
    int sbr = t>>2, sq8 = (t&3)*8;
    const __nv_bfloat16* gBh = g_wth + (size_t)(n0+sbr)*CC + sq8;
    const __nv_bfloat16* gBl = g_wtl + (size_t)(n0+sbr)*CC + sq8;
    uint32_t doffB = (uint32_t)(sbr*QROW + sq8)*2;

    float acc[2][4][4];
    #pragma unroll
    for (int mt=0;mt<2;mt++)
        #pragma unroll
        for (int nt=0;nt<4;nt++)
            #pragma unroll
            for (int i=0;i<4;i++) acc[mt][nt][i]=0.f;

    {
        uint32_t dA = sb + doffA, dB = sb + doffB;
        CP16(dA+QAH, gAh);  CP16(dA+QAH+16, gAh+8);
        CP16(dA+QAL, gAl);  CP16(dA+QAL+16, gAl+8);
        CP16(dB+QBH, gBh);
        CP16(dB+QBL, gBl);
        asm volatile("cp.async.commit_group;" ::: "memory");
    }

    const int KB = CC/32;  // 16
    for (int c=0; c<KB; c++){
        asm volatile("cp.async.wait_group 0;" ::: "memory");
        __syncthreads();
        if (c+1<KB){
            int s = (c+1)&1;
            uint32_t dA = sb + s*QBUF + doffA, dB = sb + s*QBUF + doffB;
            int koff = (c+1)*32;
            CP16(dA+QAH, gAh+koff);  CP16(dA+QAH+16, gAh+koff+8);
            CP16(dA+QAL, gAl+koff);  CP16(dA+QAL+16, gAl+koff+8);
            CP16(dB+QBH, gBh+koff);
            CP16(dB+QBL, gBl+koff);
            asm volatile("cp.async.commit_group;" ::: "memory");
        }
        uint32_t bAh = sb + (c&1)*QBUF + QAH;
        uint32_t bAl = sb + (c&1)*QBUF + QAL;
        uint32_t bBh = sb + (c&1)*QBUF + QBH;
        uint32_t bBl = sb + (c&1)*QBUF + QBL;

        #pragma unroll
        for (int ks=0; ks<2; ks++){
            int k0 = ks*16;
            uint32_t aoff = ((m0w + (l&15))*QROW + k0 + (l>>4)*8)*2;
            uint32_t ah[2][4], al[2][4];
            LDSM4(ah[0], bAh + aoff);
            LDSM4(ah[1], bAh + aoff + 16*QROW*2);
            LDSM4(al[0], bAl + aoff);
            LDSM4(al[1], bAl + aoff + 16*QROW*2);
            uint32_t boff = ((n0w + (l>>4)*8 + (l&7))*QROW + k0 + ((l>>3)&1)*8)*2;
            uint32_t bh[4][2];
            #pragma unroll
            for (int np=0; np<2; np++){
                uint32_t r4[4];
                LDSM4(r4, bBh + boff + np*16*QROW*2);
                bh[np*2][0]=r4[0]; bh[np*2][1]=r4[1];
                bh[np*2+1][0]=r4[2]; bh[np*2+1][1]=r4[3];
            }
            #pragma unroll
            for (int mt=0; mt<2; mt++)
                #pragma unroll
                for (int nt=0; nt<4; nt++)
                    MMA16816(acc[mt][nt], ah[mt], bh[nt]);
            #pragma unroll
            for (int mt=0; mt<2; mt++)
                #pragma unroll
                for (int nt=0; nt<4; nt++)
                    MMA16816(acc[mt][nt], al[mt], bh[nt]);
            #pragma unroll
            for (int np=0; np<2; np++){
                uint32_t r4[4];
                LDSM4(r4, bBl + boff + np*16*QROW*2);
                bh[np*2][0]=r4[0]; bh[np*2][1]=r4[1];
                bh[np*2+1][0]=r4[2]; bh[np*2+1][1]=r4[3];
            }
            #pragma unroll
            for (int mt=0; mt<2; mt++)
                #pragma unroll
                for (int nt=0; nt<4; nt++)
                    MMA16816(acc[mt][nt], ah[mt], bh[nt]);
        }
        __syncthreads();
    }

    int g = l>>2, q = l&3;
    #pragma unroll
    for (int mt=0; mt<2; mt++){
        #pragma unroll
        for (int rr=0; rr<2; rr++){
            int row = m0 + m0w + mt*16 + rr*8 + g;
            #pragma unroll
            for (int nt=0; nt<4; nt++){
                int col = n0 + n0w + nt*8 + q*2;
                float2 b2 = *(const float2*)&g_bcat[col];
                *(float2*)&g_proj[(size_t)row*NP + col] =
                    make_float2(acc[mt][nt][rr*2+0]+b2.x, acc[mt][nt][rr*2+1]+b2.y);
            }
        }
    }
}

// ================= query GEMM via mma.sync (hi/lo) + folded LN + gate blend =================
__global__ void __launch_bounds__(256,2) query_gemm()
{
    extern __shared__ __align__(16) char smq[];
    uint32_t sb = (uint32_t)__cvta_generic_to_shared(smq);
    int t = threadIdx.x;
    int m0 = blockIdx.x*128;
    int w = t>>5, l = t&31;
    int wm = w>>1, wn = w&1;
    int m0w = wm*32, n0w = wn*32;

    int sr = t>>1, skh = (t&1)*16;
    const __nv_bfloat16* gAh = g_fh + (size_t)(m0+sr)*CF + skh;
    const __nv_bfloat16* gAl = g_fl + (size_t)(m0+sr)*CF + skh;
    uint32_t doffA = (uint32_t)(sr*QROW + skh)*2;
    int sbr = t>>2, sq8 = (t&3)*8;
    const __nv_bfloat16* gBh = g_wqh + (size_t)sbr*CF + sq8;
    const __nv_bfloat16* gBl = g_wql + (size_t)sbr*CF + sq8;
    uint32_t doffB = (uint32_t)(sbr*QROW + sq8)*2;

    float acc[2][4][4];
    #pragma unroll
    for (int mt=0;mt<2;mt++)
        #pragma unroll
        for (int nt=0;nt<4;nt++)
            #pragma unroll
            for (int i=0;i<4;i++) acc[mt][nt][i]=0.f;

    {
        uint32_t dA = sb + doffA, dB = sb + doffB;
        CP16(dA+QAH, gAh);  CP16(dA+QAH+16, gAh+8);
        CP16(dA+QAL, gAl);  CP16(dA+QAL+16, gAl+8);
        CP16(dB+QBH, gBh);
        CP16(dB+QBL, gBl);
        asm volatile("cp.async.commit_group;" ::: "memory");
    }

    const int KB = CF/32;  // 8
    for (int c=0; c<KB; c++){
        asm volatile("cp.async.wait_group 0;" ::: "memory");
        __syncthreads();
        if (c+1<KB){
            int s = (c+1)&1;
            uint32_t dA = sb + s*QBUF + doffA, dB = sb + s*QBUF + doffB;
            int koff = (c+1)*32;
            CP16(dA+QAH, gAh+koff);  CP16(dA+QAH+16, gAh+koff+8);
            CP16(dA+QAL, gAl+koff);  CP16(dA+QAL+16, gAl+koff+8);
            CP16(dB+QBH, gBh+koff);
            CP16(dB+QBL, gBl+koff);
            asm volatile("cp.async.commit_group;" ::: "memory");
        }
        uint32_t bAh = sb + (c&1)*QBUF + QAH;
        uint32_t bAl = sb + (c&1)*QBUF + QAL;
        uint32_t bBh = sb + (c&1)*QBUF + QBH;
        uint32_t bBl = sb + (c&1)*QBUF + QBL;

        #pragma unroll
        for (int ks=0; ks<2; ks++){
            int k0 = ks*16;
            uint32_t aoff = ((m0w + (l&15))*QROW + k0 + (l>>4)*8)*2;
            uint32_t ah[2][4], al[2][4];
            LDSM4(ah[0], bAh + aoff);
            LDSM4(ah[1], bAh + aoff + 16*QROW*2);
            LDSM4(al[0], bAl + aoff);
            LDSM4(al[1], bAl + aoff + 16*QROW*2);
            uint32_t boff = ((n0w + (l>>4)*8 + (l&7))*QROW + k0 + ((l>>3)&1)*8)*2;
            uint32_t bh[4][2];
            #pragma unroll
            for (int np=0; np<2; np++){
                uint32_t r4[4];
                LDSM4(r4, bBh + boff + np*16*QROW*2);
                bh[np*2][0]=r4[0]; bh[np*2][1]=r4[1];
                bh[np*2+1][0]=r4[2]; bh[np*2+1][1]=r4[3];
            }
            #pragma unroll
            for (int mt=0; mt<2; mt++)
                #pragma unroll
                for (int nt=0; nt<4; nt++)
                    MMA16816(acc[mt][nt], ah[mt], bh[nt]);
            #pragma unroll
            for (int mt=0; mt<2; mt++)
                #pragma unroll
                for (int nt=0; nt<4; nt++)
                    MMA16816(acc[mt][nt], al[mt], bh[nt]);
            #pragma unroll
            for (int np=0; np<2; np++){
                uint32_t r4[4];
                LDSM4(r4, bBl + boff + np*16*QROW*2);
                bh[np*2][0]=r4[0]; bh[np*2][1]=r4[1];
                bh[np*2+1][0]=r4[2]; bh[np*2+1][1]=r4[3];
            }
            #pragma unroll
            for (int mt=0; mt<2; mt++)
                #pragma unroll
                for (int nt=0; nt<4; nt++)
                    MMA16816(acc[mt][nt], ah[mt], bh[nt]);
        }
        __syncthreads();
    }

    int g = l>>2, q = l&3;
    #pragma unroll
    for (int mt=0; mt<2; mt++){
        #pragma unroll
        for (int rr=0; rr<2; rr++){
            int m = m0 + m0w + mt*16 + rr*8 + g;
            float mean = g_mean[m], rstd = g_rstd[m];
            int b_ = m>>14, h = (m>>7)&127, wI = m&127;
            int mc = (b_<<12) | ((h>>1)<<6) | (wI>>1);
            float gt = g_gate[mc];
            #pragma unroll
            for (int nt=0; nt<4; nt++){
                int col = n0w + nt*8 + q*2;
                float ux = acc[mt][nt][rr*2+0];
                float uy = acc[mt][nt][rr*2+1];
                float2 dv = *(const float2*)&g_dvec[col];
                float2 cv = *(const float2*)&g_cvec[col];
                float2 qc = *(const float2*)&g_proj[(size_t)mc*NP + 64 + col];
                float2 qv, o;
                qv.x = rstd*(ux - mean*dv.x) + cv.x;
                qv.y = rstd*(uy - mean*dv.y) + cv.y;
                o.x = qv.x*gt + qc.x*(1.f-gt);
                o.y = qv.y*gt + qc.y*(1.f-gt);
                *(float2*)&g_query[(size_t)m*EE + col] = o;
            }
        }
    }
}

// ================= local attention: 16x2 coarse tile (halo 20x6) =================
#define SK_STRIDE 68
#define ATT_SMEM_BYTES ((8160 + 30720 + 8192 + 3584) * 4)
__global__ void __launch_bounds__(256) attn_kernel(float* __restrict__ out)
{
    extern __shared__ __align__(16) float sm[];
    float* sk = sm;
    float* sv = sm + 8160;
    float* sq = sm + 8160 + 30720;
    float* satt = sq + 8192;

    int j0 = blockIdx.x * 16;
    int i0 = blockIdx.y * 2;
    int b  = blockIdx.z;
    int t = threadIdx.x;

    for (int idx = t; idx < 1920; idx += 256){
        int c4 = idx & 15, cc = (idx>>4) % 20, r = idx/320;
        int ci = i0 - 2 + r, cj = j0 - 2 + cc;
        float4 v = make_float4(0.f,0.f,0.f,0.f);
        if (ci>=0 && ci<HC && cj>=0 && cj<WC)
            v = *(const float4*)&g_proj[(size_t)((b*HC+ci)*WC + cj)*NP + c4*4];
        *(float4*)&sk[(r*20+cc)*SK_STRIDE + c4*4] = v;
    }
    for (int idx = t; idx < 7680; idx += 256){
        int c4 = idx & 63, cc = (idx>>6) % 20, r = idx/1280;
        int ci = i0 - 2 + r, cj = j0 - 2 + cc;
        float4 v = make_float4(0.f,0.f,0.f,0.f);
        if (ci>=0 && ci<HC && cj>=0 && cj<WC)
            v = *(const float4*)&g_proj[(size_t)((b*HC+ci)*WC + cj)*NP + 128 + c4*4];
        *(float4*)&sv[(r*20+cc)*256 + c4*4] = v;
    }
    for (int idx = t; idx < 2048; idx += 256){
        int c4 = idx & 15, fp = idx >> 4;
        int lr = fp>>6, rem = fp&63, cp = rem>>2, q = rem&3, di = q>>1, dj = q&1;
        int h = 2*(i0+lr) + di, w = 2*(j0+cp) + dj;
        *(float4*)&sq[fp*64 + c4*4] =
            *(const float4*)&g_query[(((size_t)(b*HF+h)*WF + w)<<6) + c4*4];
    }
    __syncthreads();

    int wd = t>>5, l = t&31;
    int pr = l/5, pc = l - pr*5;
    for (int fi=0; fi<16; fi++){
        int fp = wd*16 + fi;
        int lr = fp>>6, cp = (fp>>2)&15;
        float s = -1e30f;
        if (l < 25){
            s = 0.f;
            const float* kk = &sk[((lr+pr)*20 + cp + pc)*SK_STRIDE];
            const float* qq = &sq[fp*64];
            #pragma unroll
            for (int c4=0;c4<16;c4++){
                float4 qa = *(const float4*)(qq + c4*4);
                float4 ka = *(const float4*)(kk + c4*4);
                s += qa.x*ka.x + qa.y*ka.y + qa.z*ka.z + qa.w*ka.w;
            }
        }
        float mx = s;
        #pragma unroll
        for (int o=16;o;o>>=1) mx = fmaxf(mx, __shfl_xor_sync(0xffffffffu,mx,o));
        float e = (l<25) ? __expf(s - mx) : 0.f;
        float ssum = e;
        #pragma unroll
        for (int o=16;o;o>>=1) ssum += __shfl_xor_sync(0xffffffffu,ssum,o);
        if (l<25) satt[fp*28 + l] = e / ssum;
    }
    __syncthreads();

    int cpl = t>>3, l8 = t&7;
    int lr = cpl>>4, cp = cpl&15;
    for (int cg=0; cg<8; cg++){
        int c = cg*32 + l8*4;
        ull acc[4][2];
        #pragma unroll
        for (int q=0;q<4;q++){ acc[q][0]=pk2(0.f,0.f); acc[q][1]=pk2(0.f,0.f); }
        #pragma unroll
        for (int p=0;p<25;p++){
            int ppr = p/5, ppc = p - ppr*5;
            const ull* vp = (const ull*)&sv[((lr+ppr)*20 + cp + ppc)*256 + c];
            ull v01 = vp[0], v23 = vp[1];
            #pragma unroll
            for (int q=0;q<4;q++){
                float a = satt[(lr*64 + cp*4 + q)*28 + p];
                ull aP = pk2(a,a);
                ffma2(acc[q][0], aP, v01);
                ffma2(acc[q][1], aP, v23);
            }
        }
        #pragma unroll
        for (int q=0;q<4;q++){
            int di=q>>1, dj=q&1;
            int h = 2*(i0+lr)+di, w = 2*(j0+cp)+dj;
            float2 u0=upk(acc[q][0]), u1=upk(acc[q][1]);
            float4 o = make_float4(u0.x,u0.y,u1.x,u1.y);
            *(float4*)&out[(((size_t)(b*HF+h)*WF + w)<<8) + c] = o;
        }
    }
}

// ================= launch =================
extern "C" void kernel_launch(void* const* d_in, const int* in_sizes, int n_in,
                              void* d_out, int out_size)
{
    (void)in_sizes; (void)n_in; (void)out_size;
    const float* fine   = (const float*)d_in[0];
    const float* coarse = (const float*)d_in[1];
    const float* ln_f_g = (const float*)d_in[2];
    const float* ln_f_b = (const float*)d_in[3];
    const float* ln_c_g = (const float*)d_in[4];
    const float* ln_c_b = (const float*)d_in[5];
    const float* w_gate = (const float*)d_in[6];
    const float* b_gate = (const float*)d_in[7];
    const float* w_qf   = (const float*)d_in[8];
    const float* b_qf   = (const float*)d_in[9];
    const float* w_qc   = (const float*)d_in[10];
    const float* b_qc   = (const float*)d_in[11];
    const float* w_k    = (const float*)d_in[12];
    const float* b_k    = (const float*)d_in[13];
    const float* w_v    = (const float*)d_in[14];
    const float* b_v    = (const float*)d_in[15];
    float* out = (float*)d_out;

    ln_coarse_gate<<<NCOARSE, 128>>>(coarse, ln_c_g, ln_c_b, w_gate, b_gate);   // 1
    pack_w<<<CC, NP>>>(w_k, w_qc, w_v, b_k, b_qc, b_v);                          // 2
    fine_stats<<<NFINE/8, 256>>>(fine);                                          // 3
    cudaFuncSetAttribute(proj_gemm, cudaFuncAttributeMaxDynamicSharedMemorySize, GEMM_SMEM);
    proj_gemm<<<dim3(NP/64, NCOARSE/128), 256, GEMM_SMEM>>>();                   // 4  <- profiled slot
    fold_qf<<<EE, 256>>>(w_qf, b_qf, ln_f_g, ln_f_b);                            // 5
    cudaFuncSetAttribute(query_gemm, cudaFuncAttributeMaxDynamicSharedMemorySize, GEMM_SMEM);
    query_gemm<<<NFINE/128, 256, GEMM_SMEM>>>();                                 // 6
    cudaFuncSetAttribute(attn_kernel, cudaFuncAttributeMaxDynamicSharedMemorySize, ATT_SMEM_BYTES);
    attn_kernel<<<dim3(WC/16, HC/2, BB), 256, ATT_SMEM_BYTES>>>(out);            // 7
}

// round 14
// speedup vs baseline: 1.0355x; 1.0355x over previous
#include <cuda_runtime.h>
#include <cuda_bf16.h>
#include <cstdint>
#include <cstddef>

typedef unsigned long long ull;

__device__ __forceinline__ void ffma2(ull& d, ull a, ull b){
    asm("fma.rn.f32x2 %0, %1, %2, %0;" : "+l"(d) : "l"(a), "l"(b));
}
__device__ __forceinline__ ull pk2(float x, float y){
    ull r; asm("mov.b64 %0, {%1, %2};" : "=l"(r) : "f"(x), "f"(y)); return r;
}
__device__ __forceinline__ float2 upk(ull a){
    float2 r; asm("mov.b64 {%0, %1}, %2;" : "=f"(r.x), "=f"(r.y) : "l"(a)); return r;
}

#define LDSM4(r, addr) asm volatile( \
    "ldmatrix.sync.aligned.m8n8.x4.shared.b16 {%0,%1,%2,%3}, [%4];" \
    : "=r"((r)[0]),"=r"((r)[1]),"=r"((r)[2]),"=r"((r)[3]) : "r"(addr))

#define MMA16816(c, a, b) asm volatile( \
    "mma.sync.aligned.m16n8k16.row.col.f32.bf16.bf16.f32 " \
    "{%0,%1,%2,%3}, {%4,%5,%6,%7}, {%8,%9}, {%0,%1,%2,%3};" \
    : "+f"((c)[0]),"+f"((c)[1]),"+f"((c)[2]),"+f"((c)[3]) \
    : "r"((a)[0]),"r"((a)[1]),"r"((a)[2]),"r"((a)[3]), "r"((b)[0]),"r"((b)[1]))

#define CP16(dst, src) asm volatile( \
    "cp.async.cg.shared.global [%0], [%1], 16;" :: "r"(dst), "l"(src))

// ---------------- fixed shapes ----------------
#define BB 4
#define HF 128
#define WF 128
#define CF 256
#define HC 64
#define WC 64
#define CC 512
#define EE 64
#define FF 256
#define NP 384
#define NCOARSE (BB*HC*WC)   // 16384
#define NFINE   (BB*HF*WF)   // 65536

// ---------------- scratch ----------------
__device__ __nv_bfloat16 g_cnh[(size_t)NCOARSE*CC];
__device__ __nv_bfloat16 g_cnl[(size_t)NCOARSE*CC];
__device__ __nv_bfloat16 g_wth[(size_t)NP*CC];
__device__ __nv_bfloat16 g_wtl[(size_t)NP*CC];
__device__ __nv_bfloat16 g_fh[(size_t)NFINE*CF];
__device__ __nv_bfloat16 g_fl[(size_t)NFINE*CF];
__device__ __nv_bfloat16 g_wqh[(size_t)EE*CF];
__device__ __nv_bfloat16 g_wql[(size_t)EE*CF];
__device__ float g_gate[NCOARSE];
__device__ float g_proj[(size_t)NCOARSE*NP];
__device__ float g_query[(size_t)NFINE*EE];
__device__ float g_mean[NFINE];
__device__ float g_rstd[NFINE];
__device__ float g_dvec[EE];
__device__ float g_cvec[EE];
__device__ float g_bcat[NP];

__device__ __forceinline__ void split4(float4 v, uint2& hi, uint2& lo){
    __nv_bfloat16 hx=__float2bfloat16_rn(v.x), hy=__float2bfloat16_rn(v.y);
    __nv_bfloat16 hz=__float2bfloat16_rn(v.z), hw=__float2bfloat16_rn(v.w);
    __nv_bfloat16 lx=__float2bfloat16_rn(v.x-__bfloat162float(hx));
    __nv_bfloat16 ly=__float2bfloat16_rn(v.y-__bfloat162float(hy));
    __nv_bfloat16 lz=__float2bfloat16_rn(v.z-__bfloat162float(hz));
    __nv_bfloat16 lw=__float2bfloat16_rn(v.w-__bfloat162float(hw));
    __nv_bfloat162 h01; h01.x=hx; h01.y=hy;
    __nv_bfloat162 h23; h23.x=hz; h23.y=hw;
    __nv_bfloat162 l01; l01.x=lx; l01.y=ly;
    __nv_bfloat162 l23; l23.x=lz; l23.y=lw;
    hi.x=*(unsigned*)&h01; hi.y=*(unsigned*)&h23;
    lo.x=*(unsigned*)&l01; lo.y=*(unsigned*)&l23;
}

// ================= kernel 1: LN(coarse) + gate, emit bf16 hi/lo =================
__global__ void __launch_bounds__(128) ln_coarse_gate(
    const float* __restrict__ x, const float* __restrict__ g, const float* __restrict__ b,
    const float* __restrict__ wg, const float* __restrict__ bg)
{
    int row = blockIdx.x; int t = threadIdx.x;
    const float4* xr = (const float4*)(x + (size_t)row*CC);
    float4 v = xr[t];
    float s  = v.x+v.y+v.z+v.w;
    float sq = v.x*v.x+v.y*v.y+v.z*v.z+v.w*v.w;
    #pragma unroll
    for (int o=16;o;o>>=1){ s += __shfl_xor_sync(0xffffffffu,s,o); sq += __shfl_xor_sync(0xffffffffu,sq,o); }
    __shared__ float red[8];
    int wid = t>>5, l = t&31;
    if (l==0){ red[wid]=s; red[4+wid]=sq; }
    __syncthreads();
    s  = red[0]+red[1]+red[2]+red[3];
    sq = red[4]+red[5]+red[6]+red[7];
    float mean = s*(1.f/512.f);
    float var  = sq*(1.f/512.f) - mean*mean;
    float rstd = rsqrtf(var + 1e-3f);
    float4 gv = ((const float4*)g)[t];
    float4 bv = ((const float4*)b)[t];
    float4 o;
    o.x = (v.x-mean)*rstd*gv.x + bv.x;
    o.y = (v.y-mean)*rstd*gv.y + bv.y;
    o.z = (v.z-mean)*rstd*gv.z + bv.z;
    o.w = (v.w-mean)*rstd*gv.w + bv.w;
    uint2 uh, ulo;
    split4(o, uh, ulo);
    size_t off = (size_t)row*CC + t*4;
    *(uint2*)&g_cnh[off] = uh;
    *(uint2*)&g_cnl[off] = ulo;

    float4 wv = ((const float4*)wg)[t];
    float gd = o.x*wv.x + o.y*wv.y + o.z*wv.z + o.w*wv.w;
    #pragma unroll
    for (int oo=16;oo;oo>>=1) gd += __shfl_xor_sync(0xffffffffu,gd,oo);
    __syncthreads();
    if (l==0) red[wid]=gd;
    __syncthreads();
    if (t==0){
        float tot = red[0]+red[1]+red[2]+red[3] + bg[0];
        g_gate[row] = 1.f/(1.f+__expf(-tot));
    }
}

// ================= kernel 2: fine LN stats + bf16 hi/lo emit =================
__global__ void __launch_bounds__(256) fine_stats(const float* __restrict__ x)
{
    int w = threadIdx.x>>5, l = threadIdx.x&31;
    int row = blockIdx.x*8 + w;
    const float4* xr = (const float4*)(x + (size_t)row*CF);
    float4 a = xr[l], c = xr[l+32];
    float s  = a.x+a.y+a.z+a.w + c.x+c.y+c.z+c.w;
    float sq = a.x*a.x+a.y*a.y+a.z*a.z+a.w*a.w + c.x*c.x+c.y*c.y+c.z*c.z+c.w*c.w;
    #pragma unroll
    for (int o=16;o;o>>=1){ s += __shfl_xor_sync(0xffffffffu,s,o); sq += __shfl_xor_sync(0xffffffffu,sq,o); }
    if (l==0){
        float m = s*(1.f/256.f);
        g_mean[row] = m;
        g_rstd[row] = rsqrtf(sq*(1.f/256.f) - m*m + 1e-3f);
    }
    uint2 ah, al, ch, cl;
    split4(a, ah, al);
    split4(c, ch, cl);
    size_t off = (size_t)row*CF + l*4;
    *(uint2*)&g_fh[off]       = ah;
    *(uint2*)&g_fl[off]       = al;
    *(uint2*)&g_fh[off + 128] = ch;
    *(uint2*)&g_fl[off + 128] = cl;
}

// ================= pack weights: W^T hi/lo bf16 + bias =================
__global__ void __launch_bounds__(384) pack_w(
    const float* __restrict__ wk, const float* __restrict__ wqc, const float* __restrict__ wv,
    const float* __restrict__ bk, const float* __restrict__ bqc, const float* __restrict__ bv)
{
    int k = blockIdx.x; int n = threadIdx.x;
    float v;
    if (n < 64)       v = wk [k*64  + n];
    else if (n < 128) v = wqc[k*64  + (n-64)];
    else              v = wv [k*256 + (n-128)];
    __nv_bfloat16 hi = __float2bfloat16_rn(v);
    __nv_bfloat16 lo = __float2bfloat16_rn(v - __bfloat162float(hi));
    g_wth[(size_t)n*CC + k] = hi;
    g_wtl[(size_t)n*CC + k] = lo;
    if (k == 0){
        float bvv = (n<64) ? bk[n] : (n<128) ? bqc[n-64] : bv[n-128];
        g_bcat[n] = bvv;
    }
}

// ================= fold LN(fine) params into w_qf (bf16 hi/lo [n][k]) =================
__global__ void __launch_bounds__(256) fold_qf(
    const float* __restrict__ wqf, const float* __restrict__ bqf,
    const float* __restrict__ g, const float* __restrict__ bb)
{
    int n = blockIdx.x; int t = threadIdx.x;
    float wv = wqf[t*EE + n];
    float wf = g[t]*wv;
    __nv_bfloat16 hi = __float2bfloat16_rn(wf);
    __nv_bfloat16 lo = __float2bfloat16_rn(wf - __bfloat162float(hi));
    g_wqh[(size_t)n*CF + t] = hi;
    g_wql[(size_t)n*CF + t] = lo;
    float cv = bb[t]*wv;
    float wfs = wf;
    #pragma unroll
    for (int o=16;o;o>>=1){ wfs += __shfl_xor_sync(0xffffffffu,wfs,o); cv += __shfl_xor_sync(0xffffffffu,cv,o); }
    __shared__ float sd[8], sc[8];
    int wid = t>>5, l = t&31;
    if (l==0){ sd[wid]=wfs; sc[wid]=cv; }
    __syncthreads();
    if (t==0){
        float dd=0.f, cc=0.f;
        #pragma unroll
        for (int i=0;i<8;i++){ dd+=sd[i]; cc+=sc[i]; }
        g_dvec[n]=dd; g_cvec[n]=cc + bqf[n];
    }
}

// ================= projection GEMM: BM=128 BN=128 BK=32 (R12 config, redundant sync removed) =================
#define SROW 40
#define ARR 10240
#define PBUF 40960
#define PROJ_SMEM 81920
__global__ void __launch_bounds__(256,2) proj_gemm()
{
    extern __shared__ __align__(16) char smraw[];
    uint32_t sb = (uint32_t)__cvta_generic_to_shared(smraw);
    int t = threadIdx.x;
    int n0 = blockIdx.x*128, m0 = blockIdx.y*128;
    int w = t>>5, l = t&31;
    int wm = w>>1, wn = w&1;
    int m0w = wm*32, n0w = wn*64;

    int sr = t>>1, skh = (t&1)*16;
    const __nv_bfloat16* gAh = g_cnh + (size_t)(m0+sr)*CC + skh;
    const __nv_bfloat16* gAl = g_cnl + (size_t)(m0+sr)*CC + skh;
    const __nv_bfloat16* gBh = g_wth + (size_t)(n0+sr)*CC + skh;
    const __nv_bfloat16* gBl = g_wtl + (size_t)(n0+sr)*CC + skh;
    uint32_t doff = (uint32_t)(sr*SROW + skh)*2;

    float acc[2][8][4];
    #pragma unroll
    for (int mt=0;mt<2;mt++)
        #pragma unroll
        for (int nt=0;nt<8;nt++)
            #pragma unroll
            for (int i=0;i<4;i++) acc[mt][nt][i]=0.f;

    {
        uint32_t d = sb + doff;
        CP16(d,            gAh);    CP16(d+16,            gAh+8);
        CP16(d+ARR,        gAl);    CP16(d+ARR+16,        gAl+8);
        CP16(d+2*ARR,      gBh);    CP16(d+2*ARR+16,      gBh+8);
        CP16(d+3*ARR,      gBl);    CP16(d+3*ARR+16,      gBl+8);
        asm volatile("cp.async.commit_group;" ::: "memory");
    }

    for (int c=0; c<16; c++){
        asm volatile("cp.async.wait_group 0;" ::: "memory");
        __syncthreads();
        if (c+1<16){
            int s = (c+1)&1;
            uint32_t d = sb + s*PBUF + doff;
            int koff = (c+1)*32;
            CP16(d,            gAh+koff);    CP16(d+16,            gAh+koff+8);
            CP16(d+ARR,        gAl+koff);    CP16(d+ARR+16,        gAl+koff+8);
            CP16(d+2*ARR,      gBh+koff);    CP16(d+2*ARR+16,      gBh+koff+8);
            CP16(d+3*ARR,      gBl+koff);    CP16(d+3*ARR+16,      gBl+koff+8);
            asm volatile("cp.async.commit_group;" ::: "memory");
        }
        uint32_t bAh = sb + (c&1)*PBUF;
        uint32_t bAl = bAh + ARR;
        uint32_t bBh = bAh + 2*ARR;
        uint32_t bBl = bAh + 3*ARR;

        #pragma unroll
        for (int ks=0; ks<2; ks++){
            int k0 = ks*16;
            uint32_t aoff = ((m0w + (l&15))*SROW + k0 + (l>>4)*8)*2;
            uint32_t ah[2][4], al[2][4];
            LDSM4(ah[0], bAh + aoff);
            LDSM4(ah[1], bAh + aoff + 16*SROW*2);
            LDSM4(al[0], bAl + aoff);
            LDSM4(al[1], bAl + aoff + 16*SROW*2);
            uint32_t boff = ((n0w + (l>>4)*8 + (l&7))*SROW + k0 + ((l>>3)&1)*8)*2;
            uint32_t bh[8][2];
            #pragma unroll
            for (int np=0; np<4; np++){
                uint32_t r4[4];
                LDSM4(r4, bBh + boff + np*16*SROW*2);
                bh[np*2][0]=r4[0]; bh[np*2][1]=r4[1];
                bh[np*2+1][0]=r4[2]; bh[np*2+1][1]=r4[3];
            }
            #pragma unroll
            for (int mt=0; mt<2; mt++)
                #pragma unroll
                for (int nt=0; nt<8; nt++)
                    MMA16816(acc[mt][nt], ah[mt], bh[nt]);
            #pragma unroll
            for (int mt=0; mt<2; mt++)
                #pragma unroll
                for (int nt=0; nt<8; nt++)
                    MMA16816(acc[mt][nt], al[mt], bh[nt]);
            #pragma unroll
            for (int np=0; np<4; np++){
                uint32_t r4[4];
                LDSM4(r4, bBl + boff + np*16*SROW*2);
                bh[np*2][0]=r4[0]; bh[np*2][1]=r4[1];
                bh[np*2+1][0]=r4[2]; bh[np*2+1][1]=r4[3];
            }
            #pragma unroll
            for (int mt=0; mt<2; mt++)
                #pragma unroll
                for (int nt=0; nt<8; nt++)
                    MMA16816(acc[mt][nt], ah[mt], bh[nt]);
        }
        // no trailing __syncthreads: next iteration's wait+sync precedes any smem write
    }

    int g = l>>2, q = l&3;
    #pragma unroll
    for (int mt=0; mt<2; mt++){
        int row0 = m0 + m0w + mt*16 + g;
        #pragma unroll
        for (int nt=0; nt<8; nt++){
            int col = n0 + n0w + nt*8 + q*2;
            float2 b2 = *(const float2*)&g_bcat[col];
            *(float2*)&g_proj[(size_t)row0*NP + col] =
                make_float2(acc[mt][nt][0]+b2.x, acc[mt][nt][1]+b2.y);
            *(float2*)&g_proj[(size_t)(row0+8)*NP + col] =
                make_float2(acc[mt][nt][2]+b2.x, acc[mt][nt][3]+b2.y);
        }
    }
}

// ================= query GEMM via mma.sync (hi/lo) + folded LN + gate blend =================
#define QROW 40
#define QAH 0
#define QAL 10240
#define QBH 20480
#define QBL 25600
#define QBUF 30720
#define QUERY_SMEM 61440
__global__ void __launch_bounds__(256,2) query_gemm()
{
    extern __shared__ __align__(16) char smq[];
    uint32_t sb = (uint32_t)__cvta_generic_to_shared(smq);
    int t = threadIdx.x;
    int m0 = blockIdx.x*128;
    int w = t>>5, l = t&31;
    int wm = w>>1, wn = w&1;
    int m0w = wm*32, n0w = wn*32;

    int sr = t>>1, skh = (t&1)*16;
    const __nv_bfloat16* gAh = g_fh + (size_t)(m0+sr)*CF + skh;
    const __nv_bfloat16* gAl = g_fl + (size_t)(m0+sr)*CF + skh;
    uint32_t doffA = (uint32_t)(sr*QROW + skh)*2;
    int sbr = t>>2, sq8 = (t&3)*8;
    const __nv_bfloat16* gBh = g_wqh + (size_t)sbr*CF + sq8;
    const __nv_bfloat16* gBl = g_wql + (size_t)sbr*CF + sq8;
    uint32_t doffB = (uint32_t)(sbr*QROW + sq8)*2;

    float acc[2][4][4];
    #pragma unroll
    for (int mt=0;mt<2;mt++)
        #pragma unroll
        for (int nt=0;nt<4;nt++)
            #pragma unroll
            for (int i=0;i<4;i++) acc[mt][nt][i]=0.f;

    {
        uint32_t dA = sb + doffA, dB = sb + doffB;
        CP16(dA+QAH, gAh);  CP16(dA+QAH+16, gAh+8);
        CP16(dA+QAL, gAl);  CP16(dA+QAL+16, gAl+8);
        CP16(dB+QBH, gBh);
        CP16(dB+QBL, gBl);
        asm volatile("cp.async.commit_group;" ::: "memory");
    }

    const int KB = CF/32;  // 8
    for (int c=0; c<KB; c++){
        asm volatile("cp.async.wait_group 0;" ::: "memory");
        __syncthreads();
        if (c+1<KB){
            int s = (c+1)&1;
            uint32_t dA = sb + s*QBUF + doffA, dB = sb + s*QBUF + doffB;
            int koff = (c+1)*32;
            CP16(dA+QAH, gAh+koff);  CP16(dA+QAH+16, gAh+koff+8);
            CP16(dA+QAL, gAl+koff);  CP16(dA+QAL+16, gAl+koff+8);
            CP16(dB+QBH, gBh+koff);
            CP16(dB+QBL, gBl+koff);
            asm volatile("cp.async.commit_group;" ::: "memory");
        }
        uint32_t bAh = sb + (c&1)*QBUF + QAH;
        uint32_t bAl = sb + (c&1)*QBUF + QAL;
        uint32_t bBh = sb + (c&1)*QBUF + QBH;
        uint32_t bBl = sb + (c&1)*QBUF + QBL;

        #pragma unroll
        for (int ks=0; ks<2; ks++){
            int k0 = ks*16;
            uint32_t aoff = ((m0w + (l&15))*QROW + k0 + (l>>4)*8)*2;
            uint32_t ah[2][4], al[2][4];
            LDSM4(ah[0], bAh + aoff);
            LDSM4(ah[1], bAh + aoff + 16*QROW*2);
            LDSM4(al[0], bAl + aoff);
            LDSM4(al[1], bAl + aoff + 16*QROW*2);
            uint32_t boff = ((n0w + (l>>4)*8 + (l&7))*QROW + k0 + ((l>>3)&1)*8)*2;
            uint32_t bh[4][2];
            #pragma unroll
            for (int np=0; np<2; np++){
                uint32_t r4[4];
                LDSM4(r4, bBh + boff + np*16*QROW*2);
                bh[np*2][0]=r4[0]; bh[np*2][1]=r4[1];
                bh[np*2+1][0]=r4[2]; bh[np*2+1][1]=r4[3];
            }
            #pragma unroll
            for (int mt=0; mt<2; mt++)
                #pragma unroll
                for (int nt=0; nt<4; nt++)
                    MMA16816(acc[mt][nt], ah[mt], bh[nt]);
            #pragma unroll
            for (int mt=0; mt<2; mt++)
                #pragma unroll
                for (int nt=0; nt<4; nt++)
                    MMA16816(acc[mt][nt], al[mt], bh[nt]);
            #pragma unroll
            for (int np=0; np<2; np++){
                uint32_t r4[4];
                LDSM4(r4, bBl + boff + np*16*QROW*2);
                bh[np*2][0]=r4[0]; bh[np*2][1]=r4[1];
                bh[np*2+1][0]=r4[2]; bh[np*2+1][1]=r4[3];
            }
            #pragma unroll
            for (int mt=0; mt<2; mt++)
                #pragma unroll
                for (int nt=0; nt<4; nt++)
                    MMA16816(acc[mt][nt], ah[mt], bh[nt]);
        }
        // no trailing __syncthreads (see proj_gemm)
    }

    int g = l>>2, q = l&3;
    #pragma unroll
    for (int mt=0; mt<2; mt++){
        #pragma unroll
        for (int rr=0; rr<2; rr++){
            int m = m0 + m0w + mt*16 + rr*8 + g;
            float mean = g_mean[m], rstd = g_rstd[m];
            int b_ = m>>14, h = (m>>7)&127, wI = m&127;
            int mc = (b_<<12) | ((h>>1)<<6) | (wI>>1);
            float gt = g_gate[mc];
            #pragma unroll
            for (int nt=0; nt<4; nt++){
                int col = n0w + nt*8 + q*2;
                float ux = acc[mt][nt][rr*2+0];
                float uy = acc[mt][nt][rr*2+1];
                float2 dv = *(const float2*)&g_dvec[col];
                float2 cv = *(const float2*)&g_cvec[col];
                float2 qc = *(const float2*)&g_proj[(size_t)mc*NP + 64 + col];
                float2 qv, o;
                qv.x = rstd*(ux - mean*dv.x) + cv.x;
                qv.y = rstd*(uy - mean*dv.y) + cv.y;
                o.x = qv.x*gt + qc.x*(1.f-gt);
                o.y = qv.y*gt + qc.y*(1.f-gt);
                *(float2*)&g_query[(size_t)m*EE + col] = o;
            }
        }
    }
}

// ================= local attention: 16x2 coarse tile (halo 20x6) =================
#define SK_STRIDE 68
#define ATT_SMEM_BYTES ((8160 + 30720 + 8192 + 3584) * 4)
__global__ void __launch_bounds__(256) attn_kernel(float* __restrict__ out)
{
    extern __shared__ __align__(16) float sm[];
    float* sk = sm;
    float* sv = sm + 8160;
    float* sq = sm + 8160 + 30720;
    float* satt = sq + 8192;

    int j0 = blockIdx.x * 16;
    int i0 = blockIdx.y * 2;
    int b  = blockIdx.z;
    int t = threadIdx.x;

    for (int idx = t; idx < 1920; idx += 256){
        int c4 = idx & 15, cc = (idx>>4) % 20, r = idx/320;
        int ci = i0 - 2 + r, cj = j0 - 2 + cc;
        float4 v = make_float4(0.f,0.f,0.f,0.f);
        if (ci>=0 && ci<HC && cj>=0 && cj<WC)
            v = *(const float4*)&g_proj[(size_t)((b*HC+ci)*WC + cj)*NP + c4*4];
        *(float4*)&sk[(r*20+cc)*SK_STRIDE + c4*4] = v;
    }
    for (int idx = t; idx < 7680; idx += 256){
        int c4 = idx & 63, cc = (idx>>6) % 20, r = idx/1280;
        int ci = i0 - 2 + r, cj = j0 - 2 + cc;
        float4 v = make_float4(0.f,0.f,0.f,0.f);
        if (ci>=0 && ci<HC && cj>=0 && cj<WC)
            v = *(const float4*)&g_proj[(size_t)((b*HC+ci)*WC + cj)*NP + 128 + c4*4];
        *(float4*)&sv[(r*20+cc)*256 + c4*4] = v;
    }
    for (int idx = t; idx < 2048; idx += 256){
        int c4 = idx & 15, fp = idx >> 4;
        int lr = fp>>6, rem = fp&63, cp = rem>>2, q = rem&3, di = q>>1, dj = q&1;
        int h = 2*(i0+lr) + di, w = 2*(j0+cp) + dj;
        *(float4*)&sq[fp*64 + c4*4] =
            *(const float4*)&g_query[(((size_t)(b*HF+h)*WF + w)<<6) + c4*4];
    }
    __syncthreads();

    int wd = t>>5, l = t&31;
    int pr = l/5, pc = l - pr*5;
    for (int fi=0; fi<16; fi++){
        int fp = wd*16 + fi;
        int lr = fp>>6, cp = (fp>>2)&15;
        float s = -1e30f;
        if (l < 25){
            s = 0.f;
            const float* kk = &sk[((lr+pr)*20 + cp + pc)*SK_STRIDE];
            const float* qq = &sq[fp*64];
            #pragma unroll
            for (int c4=0;c4<16;c4++){
                float4 qa = *(const float4*)(qq + c4*4);
                float4 ka = *(const float4*)(kk + c4*4);
                s += qa.x*ka.x + qa.y*ka.y + qa.z*ka.z + qa.w*ka.w;
            }
        }
        float mx = s;
        #pragma unroll
        for (int o=16;o;o>>=1) mx = fmaxf(mx, __shfl_xor_sync(0xffffffffu,mx,o));
        float e = (l<25) ? __expf(s - mx) : 0.f;
        float ssum = e;
        #pragma unroll
        for (int o=16;o;o>>=1) ssum += __shfl_xor_sync(0xffffffffu,ssum,o);
        if (l<25) satt[fp*28 + l] = e / ssum;
    }
    __syncthreads();

    int cpl = t>>3, l8 = t&7;
    int lr = cpl>>4, cp = cpl&15;
    for (int cg=0; cg<8; cg++){
        int c = cg*32 + l8*4;
        ull acc[4][2];
        #pragma unroll
        for (int q=0;q<4;q++){ acc[q][0]=pk2(0.f,0.f); acc[q][1]=pk2(0.f,0.f); }
        #pragma unroll
        for (int p=0;p<25;p++){
            int ppr = p/5, ppc = p - ppr*5;
            const ull* vp = (const ull*)&sv[((lr+ppr)*20 + cp + ppc)*256 + c];
            ull v01 = vp[0], v23 = vp[1];
            #pragma unroll
            for (int q=0;q<4;q++){
                float a = satt[(lr*64 + cp*4 + q)*28 + p];
                ull aP = pk2(a,a);
                ffma2(acc[q][0], aP, v01);
                ffma2(acc[q][1], aP, v23);
            }
        }
        #pragma unroll
        for (int q=0;q<4;q++){
            int di=q>>1, dj=q&1;
            int h = 2*(i0+lr)+di, w = 2*(j0+cp)+dj;
            float2 u0=upk(acc[q][0]), u1=upk(acc[q][1]);
            float4 o = make_float4(u0.x,u0.y,u1.x,u1.y);
            *(float4*)&out[(((size_t)(b*HF+h)*WF + w)<<8) + c] = o;
        }
    }
}

// ================= launch =================
extern "C" void kernel_launch(void* const* d_in, const int* in_sizes, int n_in,
                              void* d_out, int out_size)
{
    (void)in_sizes; (void)n_in; (void)out_size;
    const float* fine   = (const float*)d_in[0];
    const float* coarse = (const float*)d_in[1];
    const float* ln_f_g = (const float*)d_in[2];
    const float* ln_f_b = (const float*)d_in[3];
    const float* ln_c_g = (const float*)d_in[4];
    const float* ln_c_b = (const float*)d_in[5];
    const float* w_gate = (const float*)d_in[6];
    const float* b_gate = (const float*)d_in[7];
    const float* w_qf   = (const float*)d_in[8];
    const float* b_qf   = (const float*)d_in[9];
    const float* w_qc   = (const float*)d_in[10];
    const float* b_qc   = (const float*)d_in[11];
    const float* w_k    = (const float*)d_in[12];
    const float* b_k    = (const float*)d_in[13];
    const float* w_v    = (const float*)d_in[14];
    const float* b_v    = (const float*)d_in[15];
    float* out = (float*)d_out;

    ln_coarse_gate<<<NCOARSE, 128>>>(coarse, ln_c_g, ln_c_b, w_gate, b_gate);   // 1
    pack_w<<<CC, NP>>>(w_k, w_qc, w_v, b_k, b_qc, b_v);                          // 2
    fine_stats<<<NFINE/8, 256>>>(fine);                                          // 3
    cudaFuncSetAttribute(proj_gemm, cudaFuncAttributeMaxDynamicSharedMemorySize, PROJ_SMEM);
    proj_gemm<<<dim3(NP/128, NCOARSE/128), 256, PROJ_SMEM>>>();                  // 4  <- profiled slot
    fold_qf<<<EE, 256>>>(w_qf, b_qf, ln_f_g, ln_f_b);                            // 5
    cudaFuncSetAttribute(query_gemm, cudaFuncAttributeMaxDynamicSharedMemorySize, QUERY_SMEM);
    query_gemm<<<NFINE/128, 256, QUERY_SMEM>>>();                                // 6
    cudaFuncSetAttribute(attn_kernel, cudaFuncAttributeMaxDynamicSharedMemorySize, ATT_SMEM_BYTES);
    attn_kernel<<<dim3(WC/16, HC/2, BB), 256, ATT_SMEM_BYTES>>>(out);            // 7
}

// round 15
// speedup vs baseline: 1.0422x; 1.0065x over previous
#include <cuda_runtime.h>
#include <cuda_bf16.h>
#include <cstdint>
#include <cstddef>

typedef unsigned long long ull;

__device__ __forceinline__ void ffma2(ull& d, ull a, ull b){
    asm("fma.rn.f32x2 %0, %1, %2, %0;" : "+l"(d) : "l"(a), "l"(b));
}
__device__ __forceinline__ ull pk2(float x, float y){
    ull r; asm("mov.b64 %0, {%1, %2};" : "=l"(r) : "f"(x), "f"(y)); return r;
}
__device__ __forceinline__ float2 upk(ull a){
    float2 r; asm("mov.b64 {%0, %1}, %2;" : "=f"(r.x), "=f"(r.y) : "l"(a)); return r;
}

#define LDSM4(r, addr) asm volatile( \
    "ldmatrix.sync.aligned.m8n8.x4.shared.b16 {%0,%1,%2,%3}, [%4];" \
    : "=r"((r)[0]),"=r"((r)[1]),"=r"((r)[2]),"=r"((r)[3]) : "r"(addr))

#define MMA16816(c, a, b) asm volatile( \
    "mma.sync.aligned.m16n8k16.row.col.f32.bf16.bf16.f32 " \
    "{%0,%1,%2,%3}, {%4,%5,%6,%7}, {%8,%9}, {%0,%1,%2,%3};" \
    : "+f"((c)[0]),"+f"((c)[1]),"+f"((c)[2]),"+f"((c)[3]) \
    : "r"((a)[0]),"r"((a)[1]),"r"((a)[2]),"r"((a)[3]), "r"((b)[0]),"r"((b)[1]))

#define CP16(dst, src) asm volatile( \
    "cp.async.cg.shared.global [%0], [%1], 16;" :: "r"(dst), "l"(src))

// ---------------- fixed shapes ----------------
#define BB 4
#define HF 128
#define WF 128
#define CF 256
#define HC 64
#define WC 64
#define CC 512
#define EE 64
#define FF 256
#define NP 384
#define NCOARSE (BB*HC*WC)   // 16384
#define NFINE   (BB*HF*WF)   // 65536

// ---------------- scratch ----------------
__device__ __nv_bfloat16 g_cnh[(size_t)NCOARSE*CC];
__device__ __nv_bfloat16 g_cnl[(size_t)NCOARSE*CC];
__device__ __nv_bfloat16 g_wth[(size_t)NP*CC];
__device__ __nv_bfloat16 g_wtl[(size_t)NP*CC];
__device__ __nv_bfloat16 g_fh[(size_t)NFINE*CF];
__device__ __nv_bfloat16 g_fl[(size_t)NFINE*CF];
__device__ __nv_bfloat16 g_wqh[(size_t)EE*CF];
__device__ __nv_bfloat16 g_wql[(size_t)EE*CF];
__device__ float g_gate[NCOARSE];
__device__ float g_proj[(size_t)NCOARSE*NP];
__device__ float g_query[(size_t)NFINE*EE];
__device__ float g_mean[NFINE];
__device__ float g_rstd[NFINE];
__device__ float g_dvec[EE];
__device__ float g_cvec[EE];
__device__ float g_bcat[NP];

__device__ __forceinline__ void split4(float4 v, uint2& hi, uint2& lo){
    __nv_bfloat16 hx=__float2bfloat16_rn(v.x), hy=__float2bfloat16_rn(v.y);
    __nv_bfloat16 hz=__float2bfloat16_rn(v.z), hw=__float2bfloat16_rn(v.w);
    __nv_bfloat16 lx=__float2bfloat16_rn(v.x-__bfloat162float(hx));
    __nv_bfloat16 ly=__float2bfloat16_rn(v.y-__bfloat162float(hy));
    __nv_bfloat16 lz=__float2bfloat16_rn(v.z-__bfloat162float(hz));
    __nv_bfloat16 lw=__float2bfloat16_rn(v.w-__bfloat162float(hw));
    __nv_bfloat162 h01; h01.x=hx; h01.y=hy;
    __nv_bfloat162 h23; h23.x=hz; h23.y=hw;
    __nv_bfloat162 l01; l01.x=lx; l01.y=ly;
    __nv_bfloat162 l23; l23.x=lz; l23.y=lw;
    hi.x=*(unsigned*)&h01; hi.y=*(unsigned*)&h23;
    lo.x=*(unsigned*)&l01; lo.y=*(unsigned*)&l23;
}

// ================= kernel 1: LN(coarse) + gate, emit bf16 hi/lo =================
__global__ void __launch_bounds__(128) ln_coarse_gate(
    const float* __restrict__ x, const float* __restrict__ g, const float* __restrict__ b,
    const float* __restrict__ wg, const float* __restrict__ bg)
{
    int row = blockIdx.x; int t = threadIdx.x;
    const float4* xr = (const float4*)(x + (size_t)row*CC);
    float4 v = xr[t];
    float s  = v.x+v.y+v.z+v.w;
    float sq = v.x*v.x+v.y*v.y+v.z*v.z+v.w*v.w;
    #pragma unroll
    for (int o=16;o;o>>=1){ s += __shfl_xor_sync(0xffffffffu,s,o); sq += __shfl_xor_sync(0xffffffffu,sq,o); }
    __shared__ float red[8];
    int wid = t>>5, l = t&31;
    if (l==0){ red[wid]=s; red[4+wid]=sq; }
    __syncthreads();
    s  = red[0]+red[1]+red[2]+red[3];
    sq = red[4]+red[5]+red[6]+red[7];
    float mean = s*(1.f/512.f);
    float var  = sq*(1.f/512.f) - mean*mean;
    float rstd = rsqrtf(var + 1e-3f);
    float4 gv = ((const float4*)g)[t];
    float4 bv = ((const float4*)b)[t];
    float4 o;
    o.x = (v.x-mean)*rstd*gv.x + bv.x;
    o.y = (v.y-mean)*rstd*gv.y + bv.y;
    o.z = (v.z-mean)*rstd*gv.z + bv.z;
    o.w = (v.w-mean)*rstd*gv.w + bv.w;
    uint2 uh, ulo;
    split4(o, uh, ulo);
    size_t off = (size_t)row*CC + t*4;
    *(uint2*)&g_cnh[off] = uh;
    *(uint2*)&g_cnl[off] = ulo;

    float4 wv = ((const float4*)wg)[t];
    float gd = o.x*wv.x + o.y*wv.y + o.z*wv.z + o.w*wv.w;
    #pragma unroll
    for (int oo=16;oo;oo>>=1) gd += __shfl_xor_sync(0xffffffffu,gd,oo);
    __syncthreads();
    if (l==0) red[wid]=gd;
    __syncthreads();
    if (t==0){
        float tot = red[0]+red[1]+red[2]+red[3] + bg[0];
        g_gate[row] = 1.f/(1.f+__expf(-tot));
    }
}

// ================= kernel 2: fine LN stats + bf16 hi/lo emit =================
__global__ void __launch_bounds__(256) fine_stats(const float* __restrict__ x)
{
    int w = threadIdx.x>>5, l = threadIdx.x&31;
    int row = blockIdx.x*8 + w;
    const float4* xr = (const float4*)(x + (size_t)row*CF);
    float4 a = xr[l], c = xr[l+32];
    float s  = a.x+a.y+a.z+a.w + c.x+c.y+c.z+c.w;
    float sq = a.x*a.x+a.y*a.y+a.z*a.z+a.w*a.w + c.x*c.x+c.y*c.y+c.z*c.z+c.w*c.w;
    #pragma unroll
    for (int o=16;o;o>>=1){ s += __shfl_xor_sync(0xffffffffu,s,o); sq += __shfl_xor_sync(0xffffffffu,sq,o); }
    if (l==0){
        float m = s*(1.f/256.f);
        g_mean[row] = m;
        g_rstd[row] = rsqrtf(sq*(1.f/256.f) - m*m + 1e-3f);
    }
    uint2 ah, al, ch, cl;
    split4(a, ah, al);
    split4(c, ch, cl);
    size_t off = (size_t)row*CF + l*4;
    *(uint2*)&g_fh[off]       = ah;
    *(uint2*)&g_fl[off]       = al;
    *(uint2*)&g_fh[off + 128] = ch;
    *(uint2*)&g_fl[off + 128] = cl;
}

// ================= pack weights: W^T hi/lo bf16 + bias =================
__global__ void __launch_bounds__(384) pack_w(
    const float* __restrict__ wk, const float* __restrict__ wqc, const float* __restrict__ wv,
    const float* __restrict__ bk, const float* __restrict__ bqc, const float* __restrict__ bv)
{
    int k = blockIdx.x; int n = threadIdx.x;
    float v;
    if (n < 64)       v = wk [k*64  + n];
    else if (n < 128) v = wqc[k*64  + (n-64)];
    else              v = wv [k*256 + (n-128)];
    __nv_bfloat16 hi = __float2bfloat16_rn(v);
    __nv_bfloat16 lo = __float2bfloat16_rn(v - __bfloat162float(hi));
    g_wth[(size_t)n*CC + k] = hi;
    g_wtl[(size_t)n*CC + k] = lo;
    if (k == 0){
        float bvv = (n<64) ? bk[n] : (n<128) ? bqc[n-64] : bv[n-128];
        g_bcat[n] = bvv;
    }
}

// ================= fold LN(fine) params into w_qf (bf16 hi/lo [n][k]) =================
__global__ void __launch_bounds__(256) fold_qf(
    const float* __restrict__ wqf, const float* __restrict__ bqf,
    const float* __restrict__ g, const float* __restrict__ bb)
{
    int n = blockIdx.x; int t = threadIdx.x;
    float wv = wqf[t*EE + n];
    float wf = g[t]*wv;
    __nv_bfloat16 hi = __float2bfloat16_rn(wf);
    __nv_bfloat16 lo = __float2bfloat16_rn(wf - __bfloat162float(hi));
    g_wqh[(size_t)n*CF + t] = hi;
    g_wql[(size_t)n*CF + t] = lo;
    float cv = bb[t]*wv;
    float wfs = wf;
    #pragma unroll
    for (int o=16;o;o>>=1){ wfs += __shfl_xor_sync(0xffffffffu,wfs,o); cv += __shfl_xor_sync(0xffffffffu,cv,o); }
    __shared__ float sd[8], sc[8];
    int wid = t>>5, l = t&31;
    if (l==0){ sd[wid]=wfs; sc[wid]=cv; }
    __syncthreads();
    if (t==0){
        float dd=0.f, cc=0.f;
        #pragma unroll
        for (int i=0;i<8;i++){ dd+=sd[i]; cc+=sc[i]; }
        g_dvec[n]=dd; g_cvec[n]=cc + bqf[n];
    }
}

// ================= projection GEMM: BM=128 BN=128 BK=32 =================
#define SROW 40
#define ARR 10240
#define PBUF 40960
#define PROJ_SMEM 81920
__global__ void __launch_bounds__(256,2) proj_gemm()
{
    extern __shared__ __align__(16) char smraw[];
    uint32_t sb = (uint32_t)__cvta_generic_to_shared(smraw);
    int t = threadIdx.x;
    int n0 = blockIdx.x*128, m0 = blockIdx.y*128;
    int w = t>>5, l = t&31;
    int wm = w>>1, wn = w&1;
    int m0w = wm*32, n0w = wn*64;

    int sr = t>>1, skh = (t&1)*16;
    const __nv_bfloat16* gAh = g_cnh + (size_t)(m0+sr)*CC + skh;
    const __nv_bfloat16* gAl = g_cnl + (size_t)(m0+sr)*CC + skh;
    const __nv_bfloat16* gBh = g_wth + (size_t)(n0+sr)*CC + skh;
    const __nv_bfloat16* gBl = g_wtl + (size_t)(n0+sr)*CC + skh;
    uint32_t doff = (uint32_t)(sr*SROW + skh)*2;

    float acc[2][8][4];
    #pragma unroll
    for (int mt=0;mt<2;mt++)
        #pragma unroll
        for (int nt=0;nt<8;nt++)
            #pragma unroll
            for (int i=0;i<4;i++) acc[mt][nt][i]=0.f;

    {
        uint32_t d = sb + doff;
        CP16(d,            gAh);    CP16(d+16,            gAh+8);
        CP16(d+ARR,        gAl);    CP16(d+ARR+16,        gAl+8);
        CP16(d+2*ARR,      gBh);    CP16(d+2*ARR+16,      gBh+8);
        CP16(d+3*ARR,      gBl);    CP16(d+3*ARR+16,      gBl+8);
        asm volatile("cp.async.commit_group;" ::: "memory");
    }

    for (int c=0; c<16; c++){
        asm volatile("cp.async.wait_group 0;" ::: "memory");
        __syncthreads();
        if (c+1<16){
            int s = (c+1)&1;
            uint32_t d = sb + s*PBUF + doff;
            int koff = (c+1)*32;
            CP16(d,            gAh+koff);    CP16(d+16,            gAh+koff+8);
            CP16(d+ARR,        gAl+koff);    CP16(d+ARR+16,        gAl+koff+8);
            CP16(d+2*ARR,      gBh+koff);    CP16(d+2*ARR+16,      gBh+koff+8);
            CP16(d+3*ARR,      gBl+koff);    CP16(d+3*ARR+16,      gBl+koff+8);
            asm volatile("cp.async.commit_group;" ::: "memory");
        }
        uint32_t bAh = sb + (c&1)*PBUF;
        uint32_t bAl = bAh + ARR;
        uint32_t bBh = bAh + 2*ARR;
        uint32_t bBl = bAh + 3*ARR;

        #pragma unroll
        for (int ks=0; ks<2; ks++){
            int k0 = ks*16;
            uint32_t aoff = ((m0w + (l&15))*SROW + k0 + (l>>4)*8)*2;
            uint32_t ah[2][4], al[2][4];
            LDSM4(ah[0], bAh + aoff);
            LDSM4(ah[1], bAh + aoff + 16*SROW*2);
            LDSM4(al[0], bAl + aoff);
            LDSM4(al[1], bAl + aoff + 16*SROW*2);
            uint32_t boff = ((n0w + (l>>4)*8 + (l&7))*SROW + k0 + ((l>>3)&1)*8)*2;
            uint32_t bh[8][2];
            #pragma unroll
            for (int np=0; np<4; np++){
                uint32_t r4[4];
                LDSM4(r4, bBh + boff + np*16*SROW*2);
                bh[np*2][0]=r4[0]; bh[np*2][1]=r4[1];
                bh[np*2+1][0]=r4[2]; bh[np*2+1][1]=r4[3];
            }
            #pragma unroll
            for (int mt=0; mt<2; mt++)
                #pragma unroll
                for (int nt=0; nt<8; nt++)
                    MMA16816(acc[mt][nt], ah[mt], bh[nt]);
            #pragma unroll
            for (int mt=0; mt<2; mt++)
                #pragma unroll
                for (int nt=0; nt<8; nt++)
                    MMA16816(acc[mt][nt], al[mt], bh[nt]);
            #pragma unroll
            for (int np=0; np<4; np++){
                uint32_t r4[4];
                LDSM4(r4, bBl + boff + np*16*SROW*2);
                bh[np*2][0]=r4[0]; bh[np*2][1]=r4[1];
                bh[np*2+1][0]=r4[2]; bh[np*2+1][1]=r4[3];
            }
            #pragma unroll
            for (int mt=0; mt<2; mt++)
                #pragma unroll
                for (int nt=0; nt<8; nt++)
                    MMA16816(acc[mt][nt], ah[mt], bh[nt]);
        }
    }

    int g = l>>2, q = l&3;
    #pragma unroll
    for (int mt=0; mt<2; mt++){
        int row0 = m0 + m0w + mt*16 + g;
        #pragma unroll
        for (int nt=0; nt<8; nt++){
            int col = n0 + n0w + nt*8 + q*2;
            float2 b2 = *(const float2*)&g_bcat[col];
            *(float2*)&g_proj[(size_t)row0*NP + col] =
                make_float2(acc[mt][nt][0]+b2.x, acc[mt][nt][1]+b2.y);
            *(float2*)&g_proj[(size_t)(row0+8)*NP + col] =
                make_float2(acc[mt][nt][2]+b2.x, acc[mt][nt][3]+b2.y);
        }
    }
}

// ================= query GEMM via mma.sync (hi/lo) + folded LN + gate blend =================
#define QROW 40
#define QAH 0
#define QAL 10240
#define QBH 20480
#define QBL 25600
#define QBUF 30720
#define QUERY_SMEM 61440
__global__ void __launch_bounds__(256,2) query_gemm()
{
    extern __shared__ __align__(16) char smq[];
    uint32_t sb = (uint32_t)__cvta_generic_to_shared(smq);
    int t = threadIdx.x;
    int m0 = blockIdx.x*128;
    int w = t>>5, l = t&31;
    int wm = w>>1, wn = w&1;
    int m0w = wm*32, n0w = wn*32;

    int sr = t>>1, skh = (t&1)*16;
    const __nv_bfloat16* gAh = g_fh + (size_t)(m0+sr)*CF + skh;
    const __nv_bfloat16* gAl = g_fl + (size_t)(m0+sr)*CF + skh;
    uint32_t doffA = (uint32_t)(sr*QROW + skh)*2;
    int sbr = t>>2, sq8 = (t&3)*8;
    const __nv_bfloat16* gBh = g_wqh + (size_t)sbr*CF + sq8;
    const __nv_bfloat16* gBl = g_wql + (size_t)sbr*CF + sq8;
    uint32_t doffB = (uint32_t)(sbr*QROW + sq8)*2;

    float acc[2][4][4];
    #pragma unroll
    for (int mt=0;mt<2;mt++)
        #pragma unroll
        for (int nt=0;nt<4;nt++)
            #pragma unroll
            for (int i=0;i<4;i++) acc[mt][nt][i]=0.f;

    {
        uint32_t dA = sb + doffA, dB = sb + doffB;
        CP16(dA+QAH, gAh);  CP16(dA+QAH+16, gAh+8);
        CP16(dA+QAL, gAl);  CP16(dA+QAL+16, gAl+8);
        CP16(dB+QBH, gBh);
        CP16(dB+QBL, gBl);
        asm volatile("cp.async.commit_group;" ::: "memory");
    }

    const int KB = CF/32;  // 8
    for (int c=0; c<KB; c++){
        asm volatile("cp.async.wait_group 0;" ::: "memory");
        __syncthreads();
        if (c+1<KB){
            int s = (c+1)&1;
            uint32_t dA = sb + s*QBUF + doffA, dB = sb + s*QBUF + doffB;
            int koff = (c+1)*32;
            CP16(dA+QAH, gAh+koff);  CP16(dA+QAH+16, gAh+koff+8);
            CP16(dA+QAL, gAl+koff);  CP16(dA+QAL+16, gAl+koff+8);
            CP16(dB+QBH, gBh+koff);
            CP16(dB+QBL, gBl+koff);
            asm volatile("cp.async.commit_group;" ::: "memory");
        }
        uint32_t bAh = sb + (c&1)*QBUF + QAH;
        uint32_t bAl = sb + (c&1)*QBUF + QAL;
        uint32_t bBh = sb + (c&1)*QBUF + QBH;
        uint32_t bBl = sb + (c&1)*QBUF + QBL;

        #pragma unroll
        for (int ks=0; ks<2; ks++){
            int k0 = ks*16;
            uint32_t aoff = ((m0w + (l&15))*QROW + k0 + (l>>4)*8)*2;
            uint32_t ah[2][4], al[2][4];
            LDSM4(ah[0], bAh + aoff);
            LDSM4(ah[1], bAh + aoff + 16*QROW*2);
            LDSM4(al[0], bAl + aoff);
            LDSM4(al[1], bAl + aoff + 16*QROW*2);
            uint32_t boff = ((n0w + (l>>4)*8 + (l&7))*QROW + k0 + ((l>>3)&1)*8)*2;
            uint32_t bh[4][2];
            #pragma unroll
            for (int np=0; np<2; np++){
                uint32_t r4[4];
                LDSM4(r4, bBh + boff + np*16*QROW*2);
                bh[np*2][0]=r4[0]; bh[np*2][1]=r4[1];
                bh[np*2+1][0]=r4[2]; bh[np*2+1][1]=r4[3];
            }
            #pragma unroll
            for (int mt=0; mt<2; mt++)
                #pragma unroll
                for (int nt=0; nt<4; nt++)
                    MMA16816(acc[mt][nt], ah[mt], bh[nt]);
            #pragma unroll
            for (int mt=0; mt<2; mt++)
                #pragma unroll
                for (int nt=0; nt<4; nt++)
                    MMA16816(acc[mt][nt], al[mt], bh[nt]);
            #pragma unroll
            for (int np=0; np<2; np++){
                uint32_t r4[4];
                LDSM4(r4, bBl + boff + np*16*QROW*2);
                bh[np*2][0]=r4[0]; bh[np*2][1]=r4[1];
                bh[np*2+1][0]=r4[2]; bh[np*2+1][1]=r4[3];
            }
            #pragma unroll
            for (int mt=0; mt<2; mt++)
                #pragma unroll
                for (int nt=0; nt<4; nt++)
                    MMA16816(acc[mt][nt], ah[mt], bh[nt]);
        }
    }

    int g = l>>2, q = l&3;
    #pragma unroll
    for (int mt=0; mt<2; mt++){
        #pragma unroll
        for (int rr=0; rr<2; rr++){
            int m = m0 + m0w + mt*16 + rr*8 + g;
            float mean = g_mean[m], rstd = g_rstd[m];
            int b_ = m>>14, h = (m>>7)&127, wI = m&127;
            int mc = (b_<<12) | ((h>>1)<<6) | (wI>>1);
            float gt = g_gate[mc];
            #pragma unroll
            for (int nt=0; nt<4; nt++){
                int col = n0w + nt*8 + q*2;
                float ux = acc[mt][nt][rr*2+0];
                float uy = acc[mt][nt][rr*2+1];
                float2 dv = *(const float2*)&g_dvec[col];
                float2 cv = *(const float2*)&g_cvec[col];
                float2 qc = *(const float2*)&g_proj[(size_t)mc*NP + 64 + col];
                float2 qv, o;
                qv.x = rstd*(ux - mean*dv.x) + cv.x;
                qv.y = rstd*(uy - mean*dv.y) + cv.y;
                o.x = qv.x*gt + qc.x*(1.f-gt);
                o.y = qv.y*gt + qc.y*(1.f-gt);
                *(float2*)&g_query[(size_t)m*EE + col] = o;
            }
        }
    }
}

// ================= local attention: 16x2 coarse tile (halo 20x6) =================
#define SK_STRIDE 68
#define ATT_SMEM_BYTES ((8160 + 30720 + 8192 + 3584) * 4)
__global__ void __launch_bounds__(256) attn_kernel(float* __restrict__ out)
{
    extern __shared__ __align__(16) float sm[];
    float* sk = sm;
    float* sv = sm + 8160;
    float* sq = sm + 8160 + 30720;
    float* satt = sq + 8192;

    int j0 = blockIdx.x * 16;
    int i0 = blockIdx.y * 2;
    int b  = blockIdx.z;
    int t = threadIdx.x;

    for (int idx = t; idx < 1920; idx += 256){
        int c4 = idx & 15, cc = (idx>>4) % 20, r = idx/320;
        int ci = i0 - 2 + r, cj = j0 - 2 + cc;
        float4 v = make_float4(0.f,0.f,0.f,0.f);
        if (ci>=0 && ci<HC && cj>=0 && cj<WC)
            v = *(const float4*)&g_proj[(size_t)((b*HC+ci)*WC + cj)*NP + c4*4];
        *(float4*)&sk[(r*20+cc)*SK_STRIDE + c4*4] = v;
    }
    for (int idx = t; idx < 7680; idx += 256){
        int c4 = idx & 63, cc = (idx>>6) % 20, r = idx/1280;
        int ci = i0 - 2 + r, cj = j0 - 2 + cc;
        float4 v = make_float4(0.f,0.f,0.f,0.f);
        if (ci>=0 && ci<HC && cj>=0 && cj<WC)
            v = *(const float4*)&g_proj[(size_t)((b*HC+ci)*WC + cj)*NP + 128 + c4*4];
        *(float4*)&sv[(r*20+cc)*256 + c4*4] = v;
    }
    for (int idx = t; idx < 2048; idx += 256){
        int c4 = idx & 15, fp = idx >> 4;
        int lr = fp>>6, rem = fp&63, cp = rem>>2, q = rem&3, di = q>>1, dj = q&1;
        int h = 2*(i0+lr) + di, w = 2*(j0+cp) + dj;
        *(float4*)&sq[fp*64 + c4*4] =
            *(const float4*)&g_query[(((size_t)(b*HF+h)*WF + w)<<6) + c4*4];
    }
    __syncthreads();

    int wd = t>>5, l = t&31;
    int pr = l/5, pc = l - pr*5;
    for (int fi=0; fi<16; fi++){
        int fp = wd*16 + fi;
        int lr = fp>>6, cp = (fp>>2)&15;
        float s = -1e30f;
        if (l < 25){
            s = 0.f;
            const float* kk = &sk[((lr+pr)*20 + cp + pc)*SK_STRIDE];
            const float* qq = &sq[fp*64];
            #pragma unroll
            for (int c4=0;c4<16;c4++){
                float4 qa = *(const float4*)(qq + c4*4);
                float4 ka = *(const float4*)(kk + c4*4);
                s += qa.x*ka.x + qa.y*ka.y + qa.z*ka.z + qa.w*ka.w;
            }
        }
        float mx = s;
        #pragma unroll
        for (int o=16;o;o>>=1) mx = fmaxf(mx, __shfl_xor_sync(0xffffffffu,mx,o));
        float e = (l<25) ? __expf(s - mx) : 0.f;
        float ssum = e;
        #pragma unroll
        for (int o=16;o;o>>=1) ssum += __shfl_xor_sync(0xffffffffu,ssum,o);
        if (l<25) satt[fp*28 + l] = e / ssum;
    }
    __syncthreads();

    int cpl = t>>3, l8 = t&7;
    int lr = cpl>>4, cp = cpl&15;
    for (int cg=0; cg<8; cg++){
        int c = cg*32 + l8*4;
        ull acc[4][2];
        #pragma unroll
        for (int q=0;q<4;q++){ acc[q][0]=pk2(0.f,0.f); acc[q][1]=pk2(0.f,0.f); }
        #pragma unroll
        for (int p=0;p<25;p++){
            int ppr = p/5, ppc = p - ppr*5;
            const ull* vp = (const ull*)&sv[((lr+ppr)*20 + cp + ppc)*256 + c];
            ull v01 = vp[0], v23 = vp[1];
            #pragma unroll
            for (int q=0;q<4;q++){
                float a = satt[(lr*64 + cp*4 + q)*28 + p];
                ull aP = pk2(a,a);
                ffma2(acc[q][0], aP, v01);
                ffma2(acc[q][1], aP, v23);
            }
        }
        #pragma unroll
        for (int q=0;q<4;q++){
            int di=q>>1, dj=q&1;
            int h = 2*(i0+lr)+di, w = 2*(j0+cp)+dj;
            float2 u0=upk(acc[q][0]), u1=upk(acc[q][1]);
            float4 o = make_float4(u0.x,u0.y,u1.x,u1.y);
            *(float4*)&out[(((size_t)(b*HF+h)*WF + w)<<8) + c] = o;
        }
    }
}

// ================= launch: dual-stream fork so fine_stats/fold overlap proj =================
extern "C" void kernel_launch(void* const* d_in, const int* in_sizes, int n_in,
                              void* d_out, int out_size)
{
    (void)in_sizes; (void)n_in; (void)out_size;
    const float* fine   = (const float*)d_in[0];
    const float* coarse = (const float*)d_in[1];
    const float* ln_f_g = (const float*)d_in[2];
    const float* ln_f_b = (const float*)d_in[3];
    const float* ln_c_g = (const float*)d_in[4];
    const float* ln_c_b = (const float*)d_in[5];
    const float* w_gate = (const float*)d_in[6];
    const float* b_gate = (const float*)d_in[7];
    const float* w_qf   = (const float*)d_in[8];
    const float* b_qf   = (const float*)d_in[9];
    const float* w_qc   = (const float*)d_in[10];
    const float* b_qc   = (const float*)d_in[11];
    const float* w_k    = (const float*)d_in[12];
    const float* b_k    = (const float*)d_in[13];
    const float* w_v    = (const float*)d_in[14];
    const float* b_v    = (const float*)d_in[15];
    float* out = (float*)d_out;

    cudaFuncSetAttribute(proj_gemm, cudaFuncAttributeMaxDynamicSharedMemorySize, PROJ_SMEM);
    cudaFuncSetAttribute(query_gemm, cudaFuncAttributeMaxDynamicSharedMemorySize, QUERY_SMEM);
    cudaFuncSetAttribute(attn_kernel, cudaFuncAttributeMaxDynamicSharedMemorySize, ATT_SMEM_BYTES);

    cudaStream_t s2;
    cudaStreamCreate(&s2);
    cudaEvent_t e0, e2;
    cudaEventCreateWithFlags(&e0, cudaEventDisableTiming);
    cudaEventCreateWithFlags(&e2, cudaEventDisableTiming);

    // fork side stream off the capture-origin (default) stream
    cudaEventRecord(e0, 0);
    cudaStreamWaitEvent(s2, e0, 0);

    // side stream: fine-path prep (independent of coarse path)
    fine_stats<<<NFINE/8, 256, 0, s2>>>(fine);
    fold_qf<<<EE, 256, 0, s2>>>(w_qf, b_qf, ln_f_g, ln_f_b);
    cudaEventRecord(e2, s2);

    // main stream: coarse path
    ln_coarse_gate<<<NCOARSE, 128>>>(coarse, ln_c_g, ln_c_b, w_gate, b_gate);
    pack_w<<<CC, NP>>>(w_k, w_qc, w_v, b_k, b_qc, b_v);
    proj_gemm<<<dim3(NP/128, NCOARSE/128), 256, PROJ_SMEM>>>();

    // join: query needs proj (main) + fine/fold (side)
    cudaStreamWaitEvent(0, e2, 0);
    query_gemm<<<NFINE/128, 256, QUERY_SMEM>>>();
    attn_kernel<<<dim3(WC/16, HC/2, BB), 256, ATT_SMEM_BYTES>>>(out);
}

// round 17
// speedup vs baseline: 1.0474x; 1.0050x over previous
#include <cuda_runtime.h>
#include <cuda_bf16.h>
#include <cstdint>
#include <cstddef>

typedef unsigned long long ull;

__device__ __forceinline__ void ffma2(ull& d, ull a, ull b){
    asm("fma.rn.f32x2 %0, %1, %2, %0;" : "+l"(d) : "l"(a), "l"(b));
}
__device__ __forceinline__ ull pk2(float x, float y){
    ull r; asm("mov.b64 %0, {%1, %2};" : "=l"(r) : "f"(x), "f"(y)); return r;
}
__device__ __forceinline__ float2 upk(ull a){
    float2 r; asm("mov.b64 {%0, %1}, %2;" : "=f"(r.x), "=f"(r.y) : "l"(a)); return r;
}

#define LDSM4(r, addr) asm volatile( \
    "ldmatrix.sync.aligned.m8n8.x4.shared.b16 {%0,%1,%2,%3}, [%4];" \
    : "=r"((r)[0]),"=r"((r)[1]),"=r"((r)[2]),"=r"((r)[3]) : "r"(addr))

#define MMA16816(c, a, b) asm volatile( \
    "mma.sync.aligned.m16n8k16.row.col.f32.bf16.bf16.f32 " \
    "{%0,%1,%2,%3}, {%4,%5,%6,%7}, {%8,%9}, {%0,%1,%2,%3};" \
    : "+f"((c)[0]),"+f"((c)[1]),"+f"((c)[2]),"+f"((c)[3]) \
    : "r"((a)[0]),"r"((a)[1]),"r"((a)[2]),"r"((a)[3]), "r"((b)[0]),"r"((b)[1]))

#define CP16(dst, src) asm volatile( \
    "cp.async.cg.shared.global [%0], [%1], 16;" :: "r"(dst), "l"(src))

// ---------------- fixed shapes ----------------
#define BB 4
#define HF 128
#define WF 128
#define CF 256
#define HC 64
#define WC 64
#define CC 512
#define EE 64
#define FF 256
#define NP 384
#define NCOARSE (BB*HC*WC)   // 16384
#define NFINE   (BB*HF*WF)   // 65536

// ---------------- scratch ----------------
__device__ __nv_bfloat16 g_cnh[(size_t)NCOARSE*CC];
__device__ __nv_bfloat16 g_cnl[(size_t)NCOARSE*CC];
__device__ __nv_bfloat16 g_wth[(size_t)NP*CC];
__device__ __nv_bfloat16 g_wtl[(size_t)NP*CC];
__device__ __nv_bfloat16 g_fh[(size_t)NFINE*CF];
__device__ __nv_bfloat16 g_fl[(size_t)NFINE*CF];
__device__ __nv_bfloat16 g_wqh[(size_t)EE*CF];
__device__ __nv_bfloat16 g_wql[(size_t)EE*CF];
__device__ float g_gate[NCOARSE];
__device__ float g_proj[(size_t)NCOARSE*NP];
__device__ float g_query[(size_t)NFINE*EE];
__device__ float g_mean[NFINE];
__device__ float g_rstd[NFINE];
__device__ float g_dvec[EE];
__device__ float g_cvec[EE];
__device__ float g_bcat[NP];

__device__ __forceinline__ void split4(float4 v, uint2& hi, uint2& lo){
    __nv_bfloat16 hx=__float2bfloat16_rn(v.x), hy=__float2bfloat16_rn(v.y);
    __nv_bfloat16 hz=__float2bfloat16_rn(v.z), hw=__float2bfloat16_rn(v.w);
    __nv_bfloat16 lx=__float2bfloat16_rn(v.x-__bfloat162float(hx));
    __nv_bfloat16 ly=__float2bfloat16_rn(v.y-__bfloat162float(hy));
    __nv_bfloat16 lz=__float2bfloat16_rn(v.z-__bfloat162float(hz));
    __nv_bfloat16 lw=__float2bfloat16_rn(v.w-__bfloat162float(hw));
    __nv_bfloat162 h01; h01.x=hx; h01.y=hy;
    __nv_bfloat162 h23; h23.x=hz; h23.y=hw;
    __nv_bfloat162 l01; l01.x=lx; l01.y=ly;
    __nv_bfloat162 l23; l23.x=lz; l23.y=lw;
    hi.x=*(unsigned*)&h01; hi.y=*(unsigned*)&h23;
    lo.x=*(unsigned*)&l01; lo.y=*(unsigned*)&l23;
}

// ================= kernel 1: LN(coarse) + gate, emit bf16 hi/lo =================
__global__ void __launch_bounds__(128) ln_coarse_gate(
    const float* __restrict__ x, const float* __restrict__ g, const float* __restrict__ b,
    const float* __restrict__ wg, const float* __restrict__ bg)
{
    int row = blockIdx.x; int t = threadIdx.x;
    const float4* xr = (const float4*)(x + (size_t)row*CC);
    float4 v = xr[t];
    float s  = v.x+v.y+v.z+v.w;
    float sq = v.x*v.x+v.y*v.y+v.z*v.z+v.w*v.w;
    #pragma unroll
    for (int o=16;o;o>>=1){ s += __shfl_xor_sync(0xffffffffu,s,o); sq += __shfl_xor_sync(0xffffffffu,sq,o); }
    __shared__ float red[8];
    int wid = t>>5, l = t&31;
    if (l==0){ red[wid]=s; red[4+wid]=sq; }
    __syncthreads();
    s  = red[0]+red[1]+red[2]+red[3];
    sq = red[4]+red[5]+red[6]+red[7];
    float mean = s*(1.f/512.f);
    float var  = sq*(1.f/512.f) - mean*mean;
    float rstd = rsqrtf(var + 1e-3f);
    float4 gv = ((const float4*)g)[t];
    float4 bv = ((const float4*)b)[t];
    float4 o;
    o.x = (v.x-mean)*rstd*gv.x + bv.x;
    o.y = (v.y-mean)*rstd*gv.y + bv.y;
    o.z = (v.z-mean)*rstd*gv.z + bv.z;
    o.w = (v.w-mean)*rstd*gv.w + bv.w;
    uint2 uh, ulo;
    split4(o, uh, ulo);
    size_t off = (size_t)row*CC + t*4;
    *(uint2*)&g_cnh[off] = uh;
    *(uint2*)&g_cnl[off] = ulo;

    float4 wv = ((const float4*)wg)[t];
    float gd = o.x*wv.x + o.y*wv.y + o.z*wv.z + o.w*wv.w;
    #pragma unroll
    for (int oo=16;oo;oo>>=1) gd += __shfl_xor_sync(0xffffffffu,gd,oo);
    __syncthreads();
    if (l==0) red[wid]=gd;
    __syncthreads();
    if (t==0){
        float tot = red[0]+red[1]+red[2]+red[3] + bg[0];
        g_gate[row] = 1.f/(1.f+__expf(-tot));
    }
}

// ================= kernel 2: fine LN stats + bf16 hi/lo emit =================
__global__ void __launch_bounds__(256) fine_stats(const float* __restrict__ x)
{
    int w = threadIdx.x>>5, l = threadIdx.x&31;
    int row = blockIdx.x*8 + w;
    const float4* xr = (const float4*)(x + (size_t)row*CF);
    float4 a = xr[l], c = xr[l+32];
    float s  = a.x+a.y+a.z+a.w + c.x+c.y+c.z+c.w;
    float sq = a.x*a.x+a.y*a.y+a.z*a.z+a.w*a.w + c.x*c.x+c.y*c.y+c.z*c.z+c.w*c.w;
    #pragma unroll
    for (int o=16;o;o>>=1){ s += __shfl_xor_sync(0xffffffffu,s,o); sq += __shfl_xor_sync(0xffffffffu,sq,o); }
    if (l==0){
        float m = s*(1.f/256.f);
        g_mean[row] = m;
        g_rstd[row] = rsqrtf(sq*(1.f/256.f) - m*m + 1e-3f);
    }
    uint2 ah, al, ch, cl;
    split4(a, ah, al);
    split4(c, ch, cl);
    size_t off = (size_t)row*CF + l*4;
    *(uint2*)&g_fh[off]       = ah;
    *(uint2*)&g_fl[off]       = al;
    *(uint2*)&g_fh[off + 128] = ch;
    *(uint2*)&g_fl[off + 128] = cl;
}

// ================= pack weights: smem tile transpose, coalesced both sides =================
__global__ void __launch_bounds__(256) pack_w(
    const float* __restrict__ wk, const float* __restrict__ wqc, const float* __restrict__ wv,
    const float* __restrict__ bk, const float* __restrict__ bqc, const float* __restrict__ bv)
{
    __shared__ float tile[32][33];
    int nt = blockIdx.x;   // 12 tiles over n
    int kt = blockIdx.y;   // 16 tiles over k
    int tx = threadIdx.x & 31, ty = threadIdx.x >> 5;  // ty 0..7
    int n0 = nt*32;
    #pragma unroll
    for (int i=0;i<4;i++){
        int k = kt*32 + ty + i*8;
        int n = n0 + tx;
        float v;
        if (n < 64)       v = wk [k*64  + n];
        else if (n < 128) v = wqc[k*64  + (n-64)];
        else              v = wv [k*256 + (n-128)];
        tile[ty + i*8][tx] = v;
    }
    __syncthreads();
    #pragma unroll
    for (int i=0;i<4;i++){
        int nl = ty + i*8;
        int n = n0 + nl;
        int k = kt*32 + tx;
        float v = tile[tx][nl];
        __nv_bfloat16 hi = __float2bfloat16_rn(v);
        __nv_bfloat16 lo = __float2bfloat16_rn(v - __bfloat162float(hi));
        g_wth[(size_t)n*CC + k] = hi;
        g_wtl[(size_t)n*CC + k] = lo;
    }
    if (kt==0 && ty==0){
        int n = n0 + tx;
        float bvv = (n<64) ? bk[n] : (n<128) ? bqc[n-64] : bv[n-128];
        g_bcat[n] = bvv;
    }
}

// ================= fold LN(fine) params into w_qf (bf16 hi/lo [n][k]) =================
__global__ void __launch_bounds__(256) fold_qf(
    const float* __restrict__ wqf, const float* __restrict__ bqf,
    const float* __restrict__ g, const float* __restrict__ bb)
{
    int n = blockIdx.x; int t = threadIdx.x;
    float wv = wqf[t*EE + n];
    float wf = g[t]*wv;
    __nv_bfloat16 hi = __float2bfloat16_rn(wf);
    __nv_bfloat16 lo = __float2bfloat16_rn(wf - __bfloat162float(hi));
    g_wqh[(size_t)n*CF + t] = hi;
    g_wql[(size_t)n*CF + t] = lo;
    float cv = bb[t]*wv;
    float wfs = wf;
    #pragma unroll
    for (int o=16;o;o>>=1){ wfs += __shfl_xor_sync(0xffffffffu,wfs,o); cv += __shfl_xor_sync(0xffffffffu,cv,o); }
    __shared__ float sd[8], sc[8];
    int wid = t>>5, l = t&31;
    if (l==0){ sd[wid]=wfs; sc[wid]=cv; }
    __syncthreads();
    if (t==0){
        float dd=0.f, cc=0.f;
        #pragma unroll
        for (int i=0;i<8;i++){ dd+=sd[i]; cc+=sc[i]; }
        g_dvec[n]=dd; g_cvec[n]=cc + bqf[n];
    }
}

// ================= projection GEMM: BM=128 BN=128 BK=32 =================
#define SROW 40
#define ARR 10240
#define PBUF 40960
#define PROJ_SMEM 81920
__global__ void __launch_bounds__(256,2) proj_gemm()
{
    extern __shared__ __align__(16) char smraw[];
    uint32_t sb = (uint32_t)__cvta_generic_to_shared(smraw);
    int t = threadIdx.x;
    int n0 = blockIdx.x*128, m0 = blockIdx.y*128;
    int w = t>>5, l = t&31;
    int wm = w>>1, wn = w&1;
    int m0w = wm*32, n0w = wn*64;

    int sr = t>>1, skh = (t&1)*16;
    const __nv_bfloat16* gAh = g_cnh + (size_t)(m0+sr)*CC + skh;
    const __nv_bfloat16* gAl = g_cnl + (size_t)(m0+sr)*CC + skh;
    const __nv_bfloat16* gBh = g_wth + (size_t)(n0+sr)*CC + skh;
    const __nv_bfloat16* gBl = g_wtl + (size_t)(n0+sr)*CC + skh;
    uint32_t doff = (uint32_t)(sr*SROW + skh)*2;

    float acc[2][8][4];
    #pragma unroll
    for (int mt=0;mt<2;mt++)
        #pragma unroll
        for (int nt=0;nt<8;nt++)
            #pragma unroll
            for (int i=0;i<4;i++) acc[mt][nt][i]=0.f;

    {
        uint32_t d = sb + doff;
        CP16(d,            gAh);    CP16(d+16,            gAh+8);
        CP16(d+ARR,        gAl);    CP16(d+ARR+16,        gAl+8);
        CP16(d+2*ARR,      gBh);    CP16(d+2*ARR+16,      gBh+8);
        CP16(d+3*ARR,      gBl);    CP16(d+3*ARR+16,      gBl+8);
        asm volatile("cp.async.commit_group;" ::: "memory");
    }

    for (int c=0; c<16; c++){
        asm volatile("cp.async.wait_group 0;" ::: "memory");
        __syncthreads();
        if (c+1<16){
            int s = (c+1)&1;
            uint32_t d = sb + s*PBUF + doff;
            int koff = (c+1)*32;
            CP16(d,            gAh+koff);    CP16(d+16,            gAh+koff+8);
            CP16(d+ARR,        gAl+koff);    CP16(d+ARR+16,        gAl+koff+8);
            CP16(d+2*ARR,      gBh+koff);    CP16(d+2*ARR+16,      gBh+koff+8);
            CP16(d+3*ARR,      gBl+koff);    CP16(d+3*ARR+16,      gBl+koff+8);
            asm volatile("cp.async.commit_group;" ::: "memory");
        }
        uint32_t bAh = sb + (c&1)*PBUF;
        uint32_t bAl = bAh + ARR;
        uint32_t bBh = bAh + 2*ARR;
        uint32_t bBl = bAh + 3*ARR;

        #pragma unroll
        for (int ks=0; ks<2; ks++){
            int k0 = ks*16;
            uint32_t aoff = ((m0w + (l&15))*SROW + k0 + (l>>4)*8)*2;
            uint32_t ah[2][4], al[2][4];
            LDSM4(ah[0], bAh + aoff);
            LDSM4(ah[1], bAh + aoff + 16*SROW*2);
            LDSM4(al[0], bAl + aoff);
            LDSM4(al[1], bAl + aoff + 16*SROW*2);
            uint32_t boff = ((n0w + (l>>4)*8 + (l&7))*SROW + k0 + ((l>>3)&1)*8)*2;
            uint32_t bh[8][2];
            #pragma unroll
            for (int np=0; np<4; np++){
                uint32_t r4[4];
                LDSM4(r4, bBh + boff + np*16*SROW*2);
                bh[np*2][0]=r4[0]; bh[np*2][1]=r4[1];
                bh[np*2+1][0]=r4[2]; bh[np*2+1][1]=r4[3];
            }
            #pragma unroll
            for (int mt=0; mt<2; mt++)
                #pragma unroll
                for (int nt=0; nt<8; nt++)
                    MMA16816(acc[mt][nt], ah[mt], bh[nt]);
            #pragma unroll
            for (int mt=0; mt<2; mt++)
                #pragma unroll
                for (int nt=0; nt<8; nt++)
                    MMA16816(acc[mt][nt], al[mt], bh[nt]);
            #pragma unroll
            for (int np=0; np<4; np++){
                uint32_t r4[4];
                LDSM4(r4, bBl + boff + np*16*SROW*2);
                bh[np*2][0]=r4[0]; bh[np*2][1]=r4[1];
                bh[np*2+1][0]=r4[2]; bh[np*2+1][1]=r4[3];
            }
            #pragma unroll
            for (int mt=0; mt<2; mt++)
                #pragma unroll
                for (int nt=0; nt<8; nt++)
                    MMA16816(acc[mt][nt], ah[mt], bh[nt]);
        }
    }

    int g = l>>2, q = l&3;
    #pragma unroll
    for (int mt=0; mt<2; mt++){
        int row0 = m0 + m0w + mt*16 + g;
        #pragma unroll
        for (int nt=0; nt<8; nt++){
            int col = n0 + n0w + nt*8 + q*2;
            float2 b2 = *(const float2*)&g_bcat[col];
            *(float2*)&g_proj[(size_t)row0*NP + col] =
                make_float2(acc[mt][nt][0]+b2.x, acc[mt][nt][1]+b2.y);
            *(float2*)&g_proj[(size_t)(row0+8)*NP + col] =
                make_float2(acc[mt][nt][2]+b2.x, acc[mt][nt][3]+b2.y);
        }
    }
}

// ================= query GEMM via mma.sync (hi/lo) + folded LN + gate blend =================
#define QROW 40
#define QAH 0
#define QAL 10240
#define QBH 20480
#define QBL 25600
#define QBUF 30720
#define QUERY_SMEM 61440
__global__ void __launch_bounds__(256,2) query_gemm()
{
    extern __shared__ __align__(16) char smq[];
    uint32_t sb = (uint32_t)__cvta_generic_to_shared(smq);
    int t = threadIdx.x;
    int m0 = blockIdx.x*128;
    int w = t>>5, l = t&31;
    int wm = w>>1, wn = w&1;
    int m0w = wm*32, n0w = wn*32;

    int sr = t>>1, skh = (t&1)*16;
    const __nv_bfloat16* gAh = g_fh + (size_t)(m0+sr)*CF + skh;
    const __nv_bfloat16* gAl = g_fl + (size_t)(m0+sr)*CF + skh;
    uint32_t doffA = (uint32_t)(sr*QROW + skh)*2;
    int sbr = t>>2, sq8 = (t&3)*8;
    const __nv_bfloat16* gBh = g_wqh + (size_t)sbr*CF + sq8;
    const __nv_bfloat16* gBl = g_wql + (size_t)sbr*CF + sq8;
    uint32_t doffB = (uint32_t)(sbr*QROW + sq8)*2;

    float acc[2][4][4];
    #pragma unroll
    for (int mt=0;mt<2;mt++)
        #pragma unroll
        for (int nt=0;nt<4;nt++)
            #pragma unroll
            for (int i=0;i<4;i++) acc[mt][nt][i]=0.f;

    {
        uint32_t dA = sb + doffA, dB = sb + doffB;
        CP16(dA+QAH, gAh);  CP16(dA+QAH+16, gAh+8);
        CP16(dA+QAL, gAl);  CP16(dA+QAL+16, gAl+8);
        CP16(dB+QBH, gBh);
        CP16(dB+QBL, gBl);
        asm volatile("cp.async.commit_group;" ::: "memory");
    }

    const int KB = CF/32;  // 8
    for (int c=0; c<KB; c++){
        asm volatile("cp.async.wait_group 0;" ::: "memory");
        __syncthreads();
        if (c+1<KB){
            int s = (c+1)&1;
            uint32_t dA = sb + s*QBUF + doffA, dB = sb + s*QBUF + doffB;
            int koff = (c+1)*32;
            CP16(dA+QAH, gAh+koff);  CP16(dA+QAH+16, gAh+koff+8);
            CP16(dA+QAL, gAl+koff);  CP16(dA+QAL+16, gAl+koff+8);
            CP16(dB+QBH, gBh+koff);
            CP16(dB+QBL, gBl+koff);
            asm volatile("cp.async.commit_group;" ::: "memory");
        }
        uint32_t bAh = sb + (c&1)*QBUF + QAH;
        uint32_t bAl = sb + (c&1)*QBUF + QAL;
        uint32_t bBh = sb + (c&1)*QBUF + QBH;
        uint32_t bBl = sb + (c&1)*QBUF + QBL;

        #pragma unroll
        for (int ks=0; ks<2; ks++){
            int k0 = ks*16;
            uint32_t aoff = ((m0w + (l&15))*QROW + k0 + (l>>4)*8)*2;
            uint32_t ah[2][4], al[2][4];
            LDSM4(ah[0], bAh + aoff);
            LDSM4(ah[1], bAh + aoff + 16*QROW*2);
            LDSM4(al[0], bAl + aoff);
            LDSM4(al[1], bAl + aoff + 16*QROW*2);
            uint32_t boff = ((n0w + (l>>4)*8 + (l&7))*QROW + k0 + ((l>>3)&1)*8)*2;
            uint32_t bh[4][2];
            #pragma unroll
            for (int np=0; np<2; np++){
                uint32_t r4[4];
                LDSM4(r4, bBh + boff + np*16*QROW*2);
                bh[np*2][0]=r4[0]; bh[np*2][1]=r4[1];
                bh[np*2+1][0]=r4[2]; bh[np*2+1][1]=r4[3];
            }
            #pragma unroll
            for (int mt=0; mt<2; mt++)
                #pragma unroll
                for (int nt=0; nt<4; nt++)
                    MMA16816(acc[mt][nt], ah[mt], bh[nt]);
            #pragma unroll
            for (int mt=0; mt<2; mt++)
                #pragma unroll
                for (int nt=0; nt<4; nt++)
                    MMA16816(acc[mt][nt], al[mt], bh[nt]);
            #pragma unroll
            for (int np=0; np<2; np++){
                uint32_t r4[4];
                LDSM4(r4, bBl + boff + np*16*QROW*2);
                bh[np*2][0]=r4[0]; bh[np*2][1]=r4[1];
                bh[np*2+1][0]=r4[2]; bh[np*2+1][1]=r4[3];
            }
            #pragma unroll
            for (int mt=0; mt<2; mt++)
                #pragma unroll
                for (int nt=0; nt<4; nt++)
                    MMA16816(acc[mt][nt], ah[mt], bh[nt]);
        }
    }

    int g = l>>2, q = l&3;
    #pragma unroll
    for (int mt=0; mt<2; mt++){
        #pragma unroll
        for (int rr=0; rr<2; rr++){
            int m = m0 + m0w + mt*16 + rr*8 + g;
            float mean = g_mean[m], rstd = g_rstd[m];
            int b_ = m>>14, h = (m>>7)&127, wI = m&127;
            int mc = (b_<<12) | ((h>>1)<<6) | (wI>>1);
            float gt = g_gate[mc];
            #pragma unroll
            for (int nt=0; nt<4; nt++){
                int col = n0w + nt*8 + q*2;
                float ux = acc[mt][nt][rr*2+0];
                float uy = acc[mt][nt][rr*2+1];
                float2 dv = *(const float2*)&g_dvec[col];
                float2 cv = *(const float2*)&g_cvec[col];
                float2 qc = *(const float2*)&g_proj[(size_t)mc*NP + 64 + col];
                float2 qv, o;
                qv.x = rstd*(ux - mean*dv.x) + cv.x;
                qv.y = rstd*(uy - mean*dv.y) + cv.y;
                o.x = qv.x*gt + qc.x*(1.f-gt);
                o.y = qv.y*gt + qc.y*(1.f-gt);
                *(float2*)&g_query[(size_t)m*EE + col] = o;
            }
        }
    }
}

// ================= local attention: 16x2 coarse tile (halo 20x6) =================
#define SK_STRIDE 68
#define ATT_SMEM_BYTES ((8160 + 30720 + 8192 + 3584) * 4)
__global__ void __launch_bounds__(256) attn_kernel(float* __restrict__ out)
{
    extern __shared__ __align__(16) float sm[];
    float* sk = sm;
    float* sv = sm + 8160;
    float* sq = sm + 8160 + 30720;
    float* satt = sq + 8192;

    int j0 = blockIdx.x * 16;
    int i0 = blockIdx.y * 2;
    int b  = blockIdx.z;
    int t = threadIdx.x;

    for (int idx = t; idx < 1920; idx += 256){
        int c4 = idx & 15, cc = (idx>>4) % 20, r = idx/320;
        int ci = i0 - 2 + r, cj = j0 - 2 + cc;
        float4 v = make_float4(0.f,0.f,0.f,0.f);
        if (ci>=0 && ci<HC && cj>=0 && cj<WC)
            v = *(const float4*)&g_proj[(size_t)((b*HC+ci)*WC + cj)*NP + c4*4];
        *(float4*)&sk[(r*20+cc)*SK_STRIDE + c4*4] = v;
    }
    for (int idx = t; idx < 7680; idx += 256){
        int c4 = idx & 63, cc = (idx>>6) % 20, r = idx/1280;
        int ci = i0 - 2 + r, cj = j0 - 2 + cc;
        float4 v = make_float4(0.f,0.f,0.f,0.f);
        if (ci>=0 && ci<HC && cj>=0 && cj<WC)
            v = *(const float4*)&g_proj[(size_t)((b*HC+ci)*WC + cj)*NP + 128 + c4*4];
        *(float4*)&sv[(r*20+cc)*256 + c4*4] = v;
    }
    for (int idx = t; idx < 2048; idx += 256){
        int c4 = idx & 15, fp = idx >> 4;
        int lr = fp>>6, rem = fp&63, cp = rem>>2, q = rem&3, di = q>>1, dj = q&1;
        int h = 2*(i0+lr) + di, w = 2*(j0+cp) + dj;
        *(float4*)&sq[fp*64 + c4*4] =
            *(const float4*)&g_query[(((size_t)(b*HF+h)*WF + w)<<6) + c4*4];
    }
    __syncthreads();

    int wd = t>>5, l = t&31;
    int pr = l/5, pc = l - pr*5;
    for (int fi=0; fi<16; fi++){
        int fp = wd*16 + fi;
        int lr = fp>>6, cp = (fp>>2)&15;
        float s = -1e30f;
        if (l < 25){
            s = 0.f;
            const float* kk = &sk[((lr+pr)*20 + cp + pc)*SK_STRIDE];
            const float* qq = &sq[fp*64];
            #pragma unroll
            for (int c4=0;c4<16;c4++){
                float4 qa = *(const float4*)(qq + c4*4);
                float4 ka = *(const float4*)(kk + c4*4);
                s += qa.x*ka.x + qa.y*ka.y + qa.z*ka.z + qa.w*ka.w;
            }
        }
        float mx = s;
        #pragma unroll
        for (int o=16;o;o>>=1) mx = fmaxf(mx, __shfl_xor_sync(0xffffffffu,mx,o));
        float e = (l<25) ? __expf(s - mx) : 0.f;
        float ssum = e;
        #pragma unroll
        for (int o=16;o;o>>=1) ssum += __shfl_xor_sync(0xffffffffu,ssum,o);
        if (l<25) satt[fp*28 + l] = e / ssum;
    }
    __syncthreads();

    int cpl = t>>3, l8 = t&7;
    int lr = cpl>>4, cp = cpl&15;
    for (int cg=0; cg<8; cg++){
        int c = cg*32 + l8*4;
        ull acc[4][2];
        #pragma unroll
        for (int q=0;q<4;q++){ acc[q][0]=pk2(0.f,0.f); acc[q][1]=pk2(0.f,0.f); }
        #pragma unroll
        for (int p=0;p<25;p++){
            int ppr = p/5, ppc = p - ppr*5;
            const ull* vp = (const ull*)&sv[((lr+ppr)*20 + cp + ppc)*256 + c];
            ull v01 = vp[0], v23 = vp[1];
            #pragma unroll
            for (int q=0;q<4;q++){
                float a = satt[(lr*64 + cp*4 + q)*28 + p];
                ull aP = pk2(a,a);
                ffma2(acc[q][0], aP, v01);
                ffma2(acc[q][1], aP, v23);
            }
        }
        #pragma unroll
        for (int q=0;q<4;q++){
            int di=q>>1, dj=q&1;
            int h = 2*(i0+lr)+di, w = 2*(j0+cp)+dj;
            float2 u0=upk(acc[q][0]), u1=upk(acc[q][1]);
            float4 o = make_float4(u0.x,u0.y,u1.x,u1.y);
            *(float4*)&out[(((size_t)(b*HF+h)*WF + w)<<8) + c] = o;
        }
    }
}

// ================= launch: R15 structure (passed clean) with transposed pack_w =================
extern "C" void kernel_launch(void* const* d_in, const int* in_sizes, int n_in,
                              void* d_out, int out_size)
{
    (void)in_sizes; (void)n_in; (void)out_size;
    const float* fine   = (const float*)d_in[0];
    const float* coarse = (const float*)d_in[1];
    const float* ln_f_g = (const float*)d_in[2];
    const float* ln_f_b = (const float*)d_in[3];
    const float* ln_c_g = (const float*)d_in[4];
    const float* ln_c_b = (const float*)d_in[5];
    const float* w_gate = (const float*)d_in[6];
    const float* b_gate = (const float*)d_in[7];
    const float* w_qf   = (const float*)d_in[8];
    const float* b_qf   = (const float*)d_in[9];
    const float* w_qc   = (const float*)d_in[10];
    const float* b_qc   = (const float*)d_in[11];
    const float* w_k    = (const float*)d_in[12];
    const float* b_k    = (const float*)d_in[13];
    const float* w_v    = (const float*)d_in[14];
    const float* b_v    = (const float*)d_in[15];
    float* out = (float*)d_out;

    cudaFuncSetAttribute(proj_gemm, cudaFuncAttributeMaxDynamicSharedMemorySize, PROJ_SMEM);
    cudaFuncSetAttribute(query_gemm, cudaFuncAttributeMaxDynamicSharedMemorySize, QUERY_SMEM);
    cudaFuncSetAttribute(attn_kernel, cudaFuncAttributeMaxDynamicSharedMemorySize, ATT_SMEM_BYTES);

    cudaStream_t s2;
    cudaStreamCreate(&s2);
    cudaEvent_t e0, e2;
    cudaEventCreateWithFlags(&e0, cudaEventDisableTiming);
    cudaEventCreateWithFlags(&e2, cudaEventDisableTiming);

    // fork side stream off the capture-origin (default) stream
    cudaEventRecord(e0, 0);
    cudaStreamWaitEvent(s2, e0, 0);

    // side stream: fine-path prep (independent of coarse path)
    fine_stats<<<NFINE/8, 256, 0, s2>>>(fine);
    fold_qf<<<EE, 256, 0, s2>>>(w_qf, b_qf, ln_f_g, ln_f_b);
    cudaEventRecord(e2, s2);

    // main stream: coarse path
    ln_coarse_gate<<<NCOARSE, 128>>>(coarse, ln_c_g, ln_c_b, w_gate, b_gate);
    pack_w<<<dim3(NP/32, CC/32), 256>>>(w_k, w_qc, w_v, b_k, b_qc, b_v);
    proj_gemm<<<dim3(NP/128, NCOARSE/128), 256, PROJ_SMEM>>>();

    // join: query needs proj (main) + fine/fold (side)
    cudaStreamWaitEvent(0, e2, 0);
    query_gemm<<<NFINE/128, 256, QUERY_SMEM>>>();
    attn_kernel<<<dim3(WC/16, HC/2, BB), 256, ATT_SMEM_BYTES>>>(out);
}